// round 3
// baseline (speedup 1.0000x reference)
#include <cuda_runtime.h>
#include <cuda_bf16.h>
#include <math.h>

// Problem constants (fixed shapes)
#define NN      20000
#define EE      320000
#define ETOT    (EE + NN)        // with self loops
#define IN_DIM  128
#define HID     64
#define HEADS   8
#define HC      (HEADS * HID)    // 512
#define OUT_DIM 128
#define NEG_SLOPE 0.2f

// ---------------- scratch (static device globals; no allocation) -------------
__device__ __align__(16) float g_h  [(size_t)NN * HC];   // linear output (gather source)
__device__ __align__(16) float g_x2 [(size_t)NN * HC];   // aggregated output / next input
__device__ __align__(16) float g_als[(size_t)NN * HEADS];
__device__ __align__(16) float g_ald[(size_t)NN * HEADS];
__device__ int g_deg     [NN];
__device__ int g_rowstart[NN + 1];
__device__ int g_cursor  [NN];
__device__ int g_csr_src [ETOT];

// ---------------- CSR build --------------------------------------------------
__global__ void k_zero_deg(int* deg, int n) {
    int i = blockIdx.x * blockDim.x + threadIdx.x;
    if (i < n) deg[i] = 0;
}

__global__ void k_count(const int* __restrict__ ei, int E, int n, int* __restrict__ deg) {
    int e = blockIdx.x * blockDim.x + threadIdx.x;
    int etot = E + n;
    if (e >= etot) return;
    int dst = (e < E) ? ei[E + e] : (e - E);
    atomicAdd(&deg[dst], 1);
}

__global__ void k_scan(const int* __restrict__ deg, int* __restrict__ rowstart,
                       int* __restrict__ cursor, int n) {
    __shared__ int sm[1024];
    int t = threadIdx.x;
    int CH = (n + 1023) >> 10;
    int lo = t * CH;
    int hi = lo + CH; if (hi > n) hi = n;
    int loc = 0;
    for (int i = lo; i < hi; i++) loc += deg[i];
    sm[t] = loc;
    __syncthreads();
    for (int off = 1; off < 1024; off <<= 1) {
        int v = (t >= off) ? sm[t - off] : 0;
        __syncthreads();
        sm[t] += v;
        __syncthreads();
    }
    int run = sm[t] - loc;  // exclusive prefix
    for (int i = lo; i < hi; i++) {
        rowstart[i] = run;
        cursor[i]   = run;
        run += deg[i];
    }
    if (t == 1023) rowstart[n] = sm[1023];
}

__global__ void k_scatter(const int* __restrict__ ei, int E, int n,
                          int* __restrict__ cursor, int* __restrict__ csr_src) {
    int e = blockIdx.x * blockDim.x + threadIdx.x;
    int etot = E + n;
    if (e >= etot) return;
    int src, dst;
    if (e < E) { src = ei[e]; dst = ei[E + e]; }
    else       { src = e - E; dst = e - E; }
    int pos = atomicAdd(&cursor[dst], 1);
    csr_src[pos] = src;
}

// ---------------- SGEMM: C[M,Nc] = A[M,K] @ B[K,Nc], fp32 -------------------
// BM=128, BN=128, BK=16, 256 threads, 8x8 per-thread microtile.
__global__ __launch_bounds__(256) void k_sgemm(
    const float* __restrict__ A, const float* __restrict__ B,
    float* __restrict__ C, int M, int K, int Nc)
{
    __shared__ float As[16][128];
    __shared__ float Bs[16][128];
    int tid = threadIdx.x;
    int tx = tid & 15, ty = tid >> 4;
    int row0 = blockIdx.y * 128;
    int col0 = blockIdx.x * 128;

    float acc[8][8];
    #pragma unroll
    for (int i = 0; i < 8; i++)
        #pragma unroll
        for (int j = 0; j < 8; j++) acc[i][j] = 0.f;

    for (int k0 = 0; k0 < K; k0 += 16) {
        #pragma unroll
        for (int i = 0; i < 2; i++) {
            int idx = tid + i * 256;          // 0..511
            int r = idx >> 2;                 // 0..127
            int kq = (idx & 3) * 4;           // 0,4,8,12
            int gr = row0 + r;
            float4 v;
            if (gr < M) v = *(const float4*)&A[(size_t)gr * K + k0 + kq];
            else        v = make_float4(0.f, 0.f, 0.f, 0.f);
            As[kq + 0][r] = v.x; As[kq + 1][r] = v.y;
            As[kq + 2][r] = v.z; As[kq + 3][r] = v.w;
        }
        #pragma unroll
        for (int i = 0; i < 2; i++) {
            int idx = tid + i * 256;
            int r = idx >> 5;                 // 0..15
            int c = (idx & 31) * 4;           // 0..124
            *(float4*)&Bs[r][c] = *(const float4*)&B[(size_t)(k0 + r) * Nc + col0 + c];
        }
        __syncthreads();
        #pragma unroll
        for (int k = 0; k < 16; k++) {
            float a[8], b[8];
            *(float4*)&a[0] = *(float4*)&As[k][ty * 8];
            *(float4*)&a[4] = *(float4*)&As[k][ty * 8 + 4];
            *(float4*)&b[0] = *(float4*)&Bs[k][tx * 8];
            *(float4*)&b[4] = *(float4*)&Bs[k][tx * 8 + 4];
            #pragma unroll
            for (int i = 0; i < 8; i++)
                #pragma unroll
                for (int j = 0; j < 8; j++)
                    acc[i][j] += a[i] * b[j];
        }
        __syncthreads();
    }
    #pragma unroll
    for (int i = 0; i < 8; i++) {
        int gr = row0 + ty * 8 + i;
        if (gr < M) {
            float* cp = &C[(size_t)gr * Nc + col0 + tx * 8];
            *(float4*)cp       = make_float4(acc[i][0], acc[i][1], acc[i][2], acc[i][3]);
            *(float4*)(cp + 4) = make_float4(acc[i][4], acc[i][5], acc[i][6], acc[i][7]);
        }
    }
}

// ---------------- per-node attention half-logits -----------------------------
// Warp per node; lane covers F = H*C/32 contiguous floats; intra-group shfl reduce.
template<int H, int C>
__global__ __launch_bounds__(256) void k_attn_logits(
    const float* __restrict__ hfeat, const float* __restrict__ a_src,
    const float* __restrict__ a_dst, float* __restrict__ als,
    float* __restrict__ ald, int n)
{
    constexpr int HCc = H * C;
    constexpr int F = HCc / 32;
    constexpr int G = C / F;     // lanes per head
    int warp = (blockIdx.x * blockDim.x + threadIdx.x) >> 5;
    int lane = threadIdx.x & 31;
    if (warp >= n) return;
    const float4* hp = (const float4*)&hfeat[(size_t)warp * HCc + lane * F];
    const float4* sp = (const float4*)&a_src[lane * F];
    const float4* dp = (const float4*)&a_dst[lane * F];
    float s1 = 0.f, s2 = 0.f;
    #pragma unroll
    for (int q = 0; q < F / 4; q++) {
        float4 v = hp[q], w1 = sp[q], w2 = dp[q];
        s1 += v.x * w1.x + v.y * w1.y + v.z * w1.z + v.w * w1.w;
        s2 += v.x * w2.x + v.y * w2.y + v.z * w2.z + v.w * w2.w;
    }
    #pragma unroll
    for (int o = 1; o < G; o <<= 1) {
        s1 += __shfl_xor_sync(0xffffffffu, s1, o);
        s2 += __shfl_xor_sync(0xffffffffu, s2, o);
    }
    if ((lane % G) == 0) {
        int hd = lane / G;
        als[(size_t)warp * H + hd] = s1;
        ald[(size_t)warp * H + hd] = s2;
    }
}

// ---------------- fused segment softmax + weighted aggregate -----------------
// Warp per destination node. 3 passes over the node's CSR row:
//   1) per-head max of leaky_relu(logit), 2) sum of exp, 3) gather-accumulate.
template<int H, int C, bool ELU>
__global__ __launch_bounds__(256) void k_gat_aggregate(
    const float* __restrict__ hfeat, const float* __restrict__ als,
    const float* __restrict__ ald, const int* __restrict__ rowstart,
    const int* __restrict__ csr_src, const float* __restrict__ bias,
    float* __restrict__ out, int n)
{
    constexpr int HCc = H * C;
    constexpr int F = HCc / 32;   // floats per lane
    constexpr int V = F / 4;      // float4s per lane
    int warp = (blockIdx.x * blockDim.x + threadIdx.x) >> 5;
    int lane = threadIdx.x & 31;
    if (warp >= n) return;
    int d = warp;
    int start = rowstart[d], end = rowstart[d + 1];

    float al_d[H];
    #pragma unroll
    for (int h = 0; h < H; h++) al_d[h] = ald[(size_t)d * H + h];

    // pass 1: per-head max
    float mx[H];
    #pragma unroll
    for (int h = 0; h < H; h++) mx[h] = -1e30f;
    for (int j = start + lane; j < end; j += 32) {
        int s = csr_src[j];
        #pragma unroll
        for (int h = 0; h < H; h++) {
            float v = als[(size_t)s * H + h] + al_d[h];
            v = (v > 0.f) ? v : NEG_SLOPE * v;
            mx[h] = fmaxf(mx[h], v);
        }
    }
    #pragma unroll
    for (int h = 0; h < H; h++)
        #pragma unroll
        for (int o = 16; o > 0; o >>= 1)
            mx[h] = fmaxf(mx[h], __shfl_xor_sync(0xffffffffu, mx[h], o));

    // pass 2: per-head sum of exp
    float smv[H];
    #pragma unroll
    for (int h = 0; h < H; h++) smv[h] = 0.f;
    for (int j = start + lane; j < end; j += 32) {
        int s = csr_src[j];
        #pragma unroll
        for (int h = 0; h < H; h++) {
            float v = als[(size_t)s * H + h] + al_d[h];
            v = (v > 0.f) ? v : NEG_SLOPE * v;
            smv[h] += __expf(v - mx[h]);
        }
    }
    #pragma unroll
    for (int h = 0; h < H; h++)
        #pragma unroll
        for (int o = 16; o > 0; o >>= 1)
            smv[h] += __shfl_xor_sync(0xffffffffu, smv[h], o);

    const int myhead = (lane * F) / C;
    float my_ald = al_d[myhead];
    float my_mx  = mx[myhead];
    float my_inv = 1.0f / (smv[myhead] + 1e-16f);

    // pass 3: weighted gather accumulate (all lanes cooperate per edge)
    float4 acc[V];
    #pragma unroll
    for (int q = 0; q < V; q++) acc[q] = make_float4(0.f, 0.f, 0.f, 0.f);
    for (int j = start; j < end; j++) {
        int s = csr_src[j];
        float v = als[(size_t)s * H + myhead] + my_ald;
        v = (v > 0.f) ? v : NEG_SLOPE * v;
        float alpha = __expf(v - my_mx) * my_inv;
        const float4* hp = (const float4*)&hfeat[(size_t)s * HCc + lane * F];
        #pragma unroll
        for (int q = 0; q < V; q++) {
            float4 t = hp[q];
            acc[q].x += alpha * t.x;
            acc[q].y += alpha * t.y;
            acc[q].z += alpha * t.z;
            acc[q].w += alpha * t.w;
        }
    }

    // epilogue: + bias, optional ELU, store
    const float4* bp = (const float4*)&bias[lane * F];
    float* op = &out[(size_t)d * HCc + lane * F];
    #pragma unroll
    for (int q = 0; q < V; q++) {
        float4 b = bp[q];
        float4 r = acc[q];
        r.x += b.x; r.y += b.y; r.z += b.z; r.w += b.w;
        if (ELU) {
            r.x = (r.x > 0.f) ? r.x : (__expf(r.x) - 1.f);
            r.y = (r.y > 0.f) ? r.y : (__expf(r.y) - 1.f);
            r.z = (r.z > 0.f) ? r.z : (__expf(r.z) - 1.f);
            r.w = (r.w > 0.f) ? r.w : (__expf(r.w) - 1.f);
        }
        *(float4*)(op + q * 4) = r;
    }
}

// ---------------- launch ------------------------------------------------------
extern "C" void kernel_launch(void* const* d_in, const int* in_sizes, int n_in,
                              void* d_out, int out_size) {
    const float* x      = (const float*)d_in[0];
    const int*   ei     = (const int*)d_in[1];
    const float* W1     = (const float*)d_in[2];
    const float* a_src1 = (const float*)d_in[3];
    const float* a_dst1 = (const float*)d_in[4];
    const float* b1     = (const float*)d_in[5];
    const float* W2     = (const float*)d_in[6];
    const float* a_src2 = (const float*)d_in[7];
    const float* a_dst2 = (const float*)d_in[8];
    const float* b2     = (const float*)d_in[9];
    const float* W3     = (const float*)d_in[10];
    const float* a_src3 = (const float*)d_in[11];
    const float* a_dst3 = (const float*)d_in[12];
    const float* b3     = (const float*)d_in[13];
    float* out = (float*)d_out;

    const int n = NN;
    const int E = in_sizes[1] / 2;
    const int etot = E + n;

    float *hbuf, *xbuf, *als, *ald;
    int *deg, *rowstart, *cursor, *csr_src;
    cudaGetSymbolAddress((void**)&hbuf,     g_h);
    cudaGetSymbolAddress((void**)&xbuf,     g_x2);
    cudaGetSymbolAddress((void**)&als,      g_als);
    cudaGetSymbolAddress((void**)&ald,      g_ald);
    cudaGetSymbolAddress((void**)&deg,      g_deg);
    cudaGetSymbolAddress((void**)&rowstart, g_rowstart);
    cudaGetSymbolAddress((void**)&cursor,   g_cursor);
    cudaGetSymbolAddress((void**)&csr_src,  g_csr_src);

    // --- CSR build (dst-sorted edge list, recomputed every call) ---
    k_zero_deg<<<(n + 255) / 256, 256>>>(deg, n);
    k_count<<<(etot + 255) / 256, 256>>>(ei, E, n, deg);
    k_scan<<<1, 1024>>>(deg, rowstart, cursor, n);
    k_scatter<<<(etot + 255) / 256, 256>>>(ei, E, n, cursor, csr_src);

    const int warp_blocks = (n + 7) / 8;   // 8 warps / 256-thread block
    dim3 g1((HC + 127) / 128, (n + 127) / 128);
    dim3 g3((OUT_DIM + 127) / 128, (n + 127) / 128);

    // --- layer 1: IN_DIM -> 8x64 (concat) + ELU ---
    k_sgemm<<<g1, 256>>>(x, W1, hbuf, n, IN_DIM, HC);
    k_attn_logits<HEADS, HID><<<warp_blocks, 256>>>(hbuf, a_src1, a_dst1, als, ald, n);
    k_gat_aggregate<HEADS, HID, true><<<warp_blocks, 256>>>(
        hbuf, als, ald, rowstart, csr_src, b1, xbuf, n);

    // --- layer 2: 512 -> 8x64 (concat) + ELU ---
    k_sgemm<<<g1, 256>>>(xbuf, W2, hbuf, n, HC, HC);
    k_attn_logits<HEADS, HID><<<warp_blocks, 256>>>(hbuf, a_src2, a_dst2, als, ald, n);
    k_gat_aggregate<HEADS, HID, true><<<warp_blocks, 256>>>(
        hbuf, als, ald, rowstart, csr_src, b2, xbuf, n);

    // --- layer 3: 512 -> 128, heads=1, no concat, no ELU, write d_out ---
    k_sgemm<<<g3, 256>>>(xbuf, W3, hbuf, n, HC, OUT_DIM);
    k_attn_logits<1, OUT_DIM><<<warp_blocks, 256>>>(hbuf, a_src3, a_dst3, als, ald, n);
    k_gat_aggregate<1, OUT_DIM, false><<<warp_blocks, 256>>>(
        hbuf, als, ald, rowstart, csr_src, b3, out, n);
}

// round 6
// speedup vs baseline: 1.5964x; 1.5964x over previous
#include <cuda_runtime.h>
#include <cuda_bf16.h>
#include <cstdint>
#include <math.h>

// Problem constants (fixed shapes)
#define NN      20000
#define EE      320000
#define ETOT    (EE + NN)
#define IN_DIM  128
#define HID     64
#define HEADS   8
#define HC      (HEADS * HID)    // 512
#define OUT_DIM 128
#define NEG_SLOPE 0.2f

// ============================ scratch buffers ================================
__device__ __align__(16) float         g_h   [(size_t)NN * HC];   // GEMM out (fp32)
__device__ __align__(16) __nv_bfloat16 g_ahi [(size_t)NN * HC];   // A hi (bf16)
__device__ __align__(16) __nv_bfloat16 g_alo [(size_t)NN * HC];   // A lo (bf16)
__device__ __align__(16) __nv_bfloat16 g_wthi[(size_t)HC * HC];   // W^T hi  [N][K]
__device__ __align__(16) __nv_bfloat16 g_wtlo[(size_t)HC * HC];   // W^T lo
__device__ __align__(16) float g_als[(size_t)NN * HEADS];
__device__ __align__(16) float g_ald[(size_t)NN * HEADS];
__device__ int g_deg     [NN];
__device__ int g_rowstart[NN + 1];
__device__ int g_cursor  [NN];
__device__ int g_csr_src [ETOT];

__device__ __forceinline__ void split2(float v, __nv_bfloat16& hi, __nv_bfloat16& lo) {
    hi = __float2bfloat16(v);
    lo = __float2bfloat16(v - __bfloat162float(hi));
}

__device__ __forceinline__ uint32_t smem_u32(const void* p) {
    uint32_t a;
    asm("{ .reg .u64 t; cvta.to.shared.u64 t, %1; cvt.u32.u64 %0, t; }"
        : "=r"(a) : "l"(p));
    return a;
}

// ================================ CSR build ==================================
__global__ void k_zero_deg(int* deg, int n) {
    int i = blockIdx.x * blockDim.x + threadIdx.x;
    if (i < n) deg[i] = 0;
}
__global__ void k_count(const int* __restrict__ ei, int E, int n, int* __restrict__ deg) {
    int e = blockIdx.x * blockDim.x + threadIdx.x;
    if (e >= E + n) return;
    int dst = (e < E) ? ei[E + e] : (e - E);
    atomicAdd(&deg[dst], 1);
}
__global__ void k_scan(const int* __restrict__ deg, int* __restrict__ rowstart,
                       int* __restrict__ cursor, int n) {
    __shared__ int sm[1024];
    int t = threadIdx.x;
    int CH = (n + 1023) >> 10;
    int lo = t * CH, hi = lo + CH; if (hi > n) hi = n;
    int loc = 0;
    for (int i = lo; i < hi; i++) loc += deg[i];
    sm[t] = loc;
    __syncthreads();
    for (int off = 1; off < 1024; off <<= 1) {
        int v = (t >= off) ? sm[t - off] : 0;
        __syncthreads();
        sm[t] += v;
        __syncthreads();
    }
    int run = sm[t] - loc;
    for (int i = lo; i < hi; i++) {
        rowstart[i] = run; cursor[i] = run; run += deg[i];
    }
    if (t == 1023) rowstart[n] = sm[1023];
}
__global__ void k_scatter(const int* __restrict__ ei, int E, int n,
                          int* __restrict__ cursor, int* __restrict__ csr_src) {
    int e = blockIdx.x * blockDim.x + threadIdx.x;
    if (e >= E + n) return;
    int src, dst;
    if (e < E) { src = ei[e]; dst = ei[E + e]; }
    else       { src = e - E; dst = e - E; }
    int pos = atomicAdd(&cursor[dst], 1);
    csr_src[pos] = src;
}

// ======================= fp32 -> bf16 hi/lo conversions ======================
__global__ void k_split_x(const float* __restrict__ x, __nv_bfloat16* __restrict__ hi,
                          __nv_bfloat16* __restrict__ lo, int total) {
    int i = blockIdx.x * blockDim.x + threadIdx.x;
    if (i >= total) return;
    split2(x[i], hi[i], lo[i]);
}
// W [K,N] fp32 -> Wt [N,K] bf16 hi/lo
__global__ void k_split_wt(const float* __restrict__ W, __nv_bfloat16* __restrict__ hi,
                           __nv_bfloat16* __restrict__ lo, int K, int N) {
    int i = blockIdx.x * blockDim.x + threadIdx.x;
    if (i >= K * N) return;
    int k = i / N, n = i % N;
    __nv_bfloat16 h, l;
    split2(W[i], h, l);
    hi[(size_t)n * K + k] = h;
    lo[(size_t)n * K + k] = l;
}

// =================== HMMA GEMM: C[M,N] = A[M,K] @ Wt[N,K]^T ==================
// bf16 hi/lo split, fp32 accumulate: D = Ah*Bh + Ah*Bl + Al*Bh.
// Tiles: BM=128, BN=128, BK=32. 8 warps (2x4), 64x32 warp tile.
// mma.sync.m16n8k16 + ldmatrix (plain-target PTX, no "a" features).

__device__ __forceinline__ void mma16816(float* d, const uint32_t* a, const uint32_t* b) {
    asm volatile(
        "mma.sync.aligned.m16n8k16.row.col.f32.bf16.bf16.f32 "
        "{%0,%1,%2,%3}, {%4,%5,%6,%7}, {%8,%9}, {%0,%1,%2,%3};"
        : "+f"(d[0]), "+f"(d[1]), "+f"(d[2]), "+f"(d[3])
        : "r"(a[0]), "r"(a[1]), "r"(a[2]), "r"(a[3]), "r"(b[0]), "r"(b[1]));
}
__device__ __forceinline__ void ldsm_x4(uint32_t* r, uint32_t addr) {
    asm volatile("ldmatrix.sync.aligned.m8n8.x4.shared.b16 {%0,%1,%2,%3}, [%4];"
                 : "=r"(r[0]), "=r"(r[1]), "=r"(r[2]), "=r"(r[3]) : "r"(addr));
}
__device__ __forceinline__ void ldsm_x2(uint32_t* r, uint32_t addr) {
    asm volatile("ldmatrix.sync.aligned.m8n8.x2.shared.b16 {%0,%1}, [%2];"
                 : "=r"(r[0]), "=r"(r[1]) : "r"(addr));
}

#define LDPAD 40   // 32 + 8 halves: 80B row stride -> conflict-free ldmatrix

__global__ __launch_bounds__(256) void k_mma_gemm(
    const __nv_bfloat16* __restrict__ Ahi, const __nv_bfloat16* __restrict__ Alo,
    const __nv_bfloat16* __restrict__ Bhi, const __nv_bfloat16* __restrict__ Blo,
    float* __restrict__ C, int M, int K, int N)
{
    __shared__ __align__(16) __nv_bfloat16 sAh[128][LDPAD];
    __shared__ __align__(16) __nv_bfloat16 sAl[128][LDPAD];
    __shared__ __align__(16) __nv_bfloat16 sBh[128][LDPAD];
    __shared__ __align__(16) __nv_bfloat16 sBl[128][LDPAD];

    const int tid = threadIdx.x;
    const int wid = tid >> 5, lane = tid & 31;
    const int wm0 = (wid & 1) * 64;          // warp m offset in tile
    const int wn0 = (wid >> 1) * 32;         // warp n offset in tile
    const int row0 = blockIdx.y * 128, col0 = blockIdx.x * 128;

    float acc[4][4][4];
    #pragma unroll
    for (int i = 0; i < 4; i++)
        #pragma unroll
        for (int j = 0; j < 4; j++)
            #pragma unroll
            for (int q = 0; q < 4; q++) acc[i][j][q] = 0.f;

    // gmem staging: each thread loads 2x uint4 (16B) per matrix per chunk
    //   idx = tid + i*256 (0..511): row = idx>>2 (0..127), qc = idx&3 (8-half col group)
    const int ldr = tid >> 2;                 // 0..63  (row for i=0; +64 for i=1)
    const int ldq = (tid & 3) * 8;            // half-col offset

    // ldmatrix base addresses (per-thread)
    const int la = lane & 15;
    const uint32_t aoffs = (uint32_t)(((la) * LDPAD + (lane >> 4) * 8) * 2);
    uint32_t aBaseH = smem_u32(&sAh[wm0][0]) + aoffs;
    uint32_t aBaseL = smem_u32(&sAl[wm0][0]) + aoffs;
    const uint32_t boffs = (uint32_t)(((la & 7) * LDPAD + ((la >> 3) & 1) * 8) * 2);
    uint32_t bBaseH = smem_u32(&sBh[wn0][0]) + boffs;
    uint32_t bBaseL = smem_u32(&sBl[wn0][0]) + boffs;

    const int nch = K >> 5;
    uint4 rAh[2], rAl[2], rBh[2], rBl[2];

    // prefetch chunk 0
    {
        const int k0 = 0;
        #pragma unroll
        for (int i = 0; i < 2; i++) {
            int r = ldr + i * 64;
            int gr = row0 + r;
            if (gr < M) {
                rAh[i] = *(const uint4*)&Ahi[(size_t)gr * K + k0 + ldq];
                rAl[i] = *(const uint4*)&Alo[(size_t)gr * K + k0 + ldq];
            } else {
                rAh[i] = make_uint4(0, 0, 0, 0);
                rAl[i] = make_uint4(0, 0, 0, 0);
            }
            rBh[i] = *(const uint4*)&Bhi[(size_t)(col0 + r) * K + k0 + ldq];
            rBl[i] = *(const uint4*)&Blo[(size_t)(col0 + r) * K + k0 + ldq];
        }
    }

    for (int ch = 0; ch < nch; ch++) {
        // store staged regs -> smem
        #pragma unroll
        for (int i = 0; i < 2; i++) {
            int r = ldr + i * 64;
            *(uint4*)&sAh[r][ldq] = rAh[i];
            *(uint4*)&sAl[r][ldq] = rAl[i];
            *(uint4*)&sBh[r][ldq] = rBh[i];
            *(uint4*)&sBl[r][ldq] = rBl[i];
        }
        __syncthreads();

        // prefetch next chunk (overlaps compute)
        if (ch + 1 < nch) {
            const int k0 = (ch + 1) << 5;
            #pragma unroll
            for (int i = 0; i < 2; i++) {
                int r = ldr + i * 64;
                int gr = row0 + r;
                if (gr < M) {
                    rAh[i] = *(const uint4*)&Ahi[(size_t)gr * K + k0 + ldq];
                    rAl[i] = *(const uint4*)&Alo[(size_t)gr * K + k0 + ldq];
                } else {
                    rAh[i] = make_uint4(0, 0, 0, 0);
                    rAl[i] = make_uint4(0, 0, 0, 0);
                }
                rBh[i] = *(const uint4*)&Bhi[(size_t)(col0 + r) * K + k0 + ldq];
                rBl[i] = *(const uint4*)&Blo[(size_t)(col0 + r) * K + k0 + ldq];
            }
        }

        // compute: 2 k16 steps
        #pragma unroll
        for (int st = 0; st < 2; st++) {
            const uint32_t ko = st * 32;   // 16 halves = 32 bytes
            uint32_t Ah[4][4], Al[4][4], Bh[4][2], Bl[4][2];
            #pragma unroll
            for (int i = 0; i < 4; i++) {
                ldsm_x4(Ah[i], aBaseH + ko + (uint32_t)(i * 16 * LDPAD * 2));
                ldsm_x4(Al[i], aBaseL + ko + (uint32_t)(i * 16 * LDPAD * 2));
            }
            #pragma unroll
            for (int j = 0; j < 4; j++) {
                ldsm_x2(Bh[j], bBaseH + ko + (uint32_t)(j * 8 * LDPAD * 2));
                ldsm_x2(Bl[j], bBaseL + ko + (uint32_t)(j * 8 * LDPAD * 2));
            }
            #pragma unroll
            for (int i = 0; i < 4; i++)
                #pragma unroll
                for (int j = 0; j < 4; j++) {
                    mma16816(acc[i][j], Ah[i], Bh[j]);
                    mma16816(acc[i][j], Ah[i], Bl[j]);
                    mma16816(acc[i][j], Al[i], Bh[j]);
                }
        }
        __syncthreads();
    }

    // epilogue: d0,d1 -> (row groupID, col 2c); d2,d3 -> (row+8)
    const int er = lane >> 2, ec = (lane & 3) * 2;
    #pragma unroll
    for (int i = 0; i < 4; i++) {
        #pragma unroll
        for (int j = 0; j < 4; j++) {
            int gr = row0 + wm0 + i * 16 + er;
            int gc = col0 + wn0 + j * 8 + ec;
            if (gr < M)
                *(float2*)&C[(size_t)gr * N + gc] = make_float2(acc[i][j][0], acc[i][j][1]);
            if (gr + 8 < M)
                *(float2*)&C[(size_t)(gr + 8) * N + gc] = make_float2(acc[i][j][2], acc[i][j][3]);
        }
    }
}

// ===================== per-node attention half-logits ========================
template<int H, int C>
__global__ __launch_bounds__(256) void k_attn_logits(
    const float* __restrict__ hfeat, const float* __restrict__ a_src,
    const float* __restrict__ a_dst, float* __restrict__ als,
    float* __restrict__ ald, int n)
{
    constexpr int HCc = H * C;
    constexpr int F = HCc / 32;
    constexpr int G = C / F;
    int warp = (blockIdx.x * blockDim.x + threadIdx.x) >> 5;
    int lane = threadIdx.x & 31;
    if (warp >= n) return;
    const float4* hp = (const float4*)&hfeat[(size_t)warp * HCc + lane * F];
    const float4* sp = (const float4*)&a_src[lane * F];
    const float4* dp = (const float4*)&a_dst[lane * F];
    float s1 = 0.f, s2 = 0.f;
    #pragma unroll
    for (int q = 0; q < F / 4; q++) {
        float4 v = hp[q], w1 = sp[q], w2 = dp[q];
        s1 += v.x * w1.x + v.y * w1.y + v.z * w1.z + v.w * w1.w;
        s2 += v.x * w2.x + v.y * w2.y + v.z * w2.z + v.w * w2.w;
    }
    #pragma unroll
    for (int o = 1; o < G; o <<= 1) {
        s1 += __shfl_xor_sync(0xffffffffu, s1, o);
        s2 += __shfl_xor_sync(0xffffffffu, s2, o);
    }
    if ((lane % G) == 0) {
        int hd = lane / G;
        als[(size_t)warp * H + hd] = s1;
        ald[(size_t)warp * H + hd] = s2;
    }
}

// ============ fused segment softmax + weighted aggregate (warp/node) =========
template<int H, int C, bool ELU, bool SPLIT>
__global__ __launch_bounds__(256) void k_gat_aggregate(
    const float* __restrict__ hfeat, const float* __restrict__ als,
    const float* __restrict__ ald, const int* __restrict__ rowstart,
    const int* __restrict__ csr_src, const float* __restrict__ bias,
    float* __restrict__ out, __nv_bfloat16* __restrict__ ohi,
    __nv_bfloat16* __restrict__ olo, int n)
{
    constexpr int HCc = H * C;
    constexpr int F = HCc / 32;
    constexpr int V = F / 4;
    int warp = (blockIdx.x * blockDim.x + threadIdx.x) >> 5;
    int lane = threadIdx.x & 31;
    if (warp >= n) return;
    int d = warp;
    int start = rowstart[d], end = rowstart[d + 1];

    float al_d[H];
    #pragma unroll
    for (int h = 0; h < H; h++) al_d[h] = ald[(size_t)d * H + h];

    float mx[H];
    #pragma unroll
    for (int h = 0; h < H; h++) mx[h] = -1e30f;
    for (int j = start + lane; j < end; j += 32) {
        int s = csr_src[j];
        #pragma unroll
        for (int h = 0; h < H; h++) {
            float v = als[(size_t)s * H + h] + al_d[h];
            v = (v > 0.f) ? v : NEG_SLOPE * v;
            mx[h] = fmaxf(mx[h], v);
        }
    }
    #pragma unroll
    for (int h = 0; h < H; h++)
        #pragma unroll
        for (int o = 16; o > 0; o >>= 1)
            mx[h] = fmaxf(mx[h], __shfl_xor_sync(0xffffffffu, mx[h], o));

    float smv[H];
    #pragma unroll
    for (int h = 0; h < H; h++) smv[h] = 0.f;
    for (int j = start + lane; j < end; j += 32) {
        int s = csr_src[j];
        #pragma unroll
        for (int h = 0; h < H; h++) {
            float v = als[(size_t)s * H + h] + al_d[h];
            v = (v > 0.f) ? v : NEG_SLOPE * v;
            smv[h] += __expf(v - mx[h]);
        }
    }
    #pragma unroll
    for (int h = 0; h < H; h++)
        #pragma unroll
        for (int o = 16; o > 0; o >>= 1)
            smv[h] += __shfl_xor_sync(0xffffffffu, smv[h], o);

    const int myhead = (lane * F) / C;
    float my_ald = al_d[myhead];
    float my_mx  = mx[myhead];
    float my_inv = 1.0f / (smv[myhead] + 1e-16f);

    float4 acc[V];
    #pragma unroll
    for (int q = 0; q < V; q++) acc[q] = make_float4(0.f, 0.f, 0.f, 0.f);
    for (int j = start; j < end; j++) {
        int s = csr_src[j];
        float v = als[(size_t)s * H + myhead] + my_ald;
        v = (v > 0.f) ? v : NEG_SLOPE * v;
        float alpha = __expf(v - my_mx) * my_inv;
        const float4* hp = (const float4*)&hfeat[(size_t)s * HCc + lane * F];
        #pragma unroll
        for (int q = 0; q < V; q++) {
            float4 t = hp[q];
            acc[q].x += alpha * t.x; acc[q].y += alpha * t.y;
            acc[q].z += alpha * t.z; acc[q].w += alpha * t.w;
        }
    }

    const float4* bp = (const float4*)&bias[lane * F];
    #pragma unroll
    for (int q = 0; q < V; q++) {
        float4 b = bp[q];
        acc[q].x += b.x; acc[q].y += b.y; acc[q].z += b.z; acc[q].w += b.w;
        if (ELU) {
            acc[q].x = (acc[q].x > 0.f) ? acc[q].x : (__expf(acc[q].x) - 1.f);
            acc[q].y = (acc[q].y > 0.f) ? acc[q].y : (__expf(acc[q].y) - 1.f);
            acc[q].z = (acc[q].z > 0.f) ? acc[q].z : (__expf(acc[q].z) - 1.f);
            acc[q].w = (acc[q].w > 0.f) ? acc[q].w : (__expf(acc[q].w) - 1.f);
        }
    }

    if (SPLIT) {
        __nv_bfloat16 hv[F], lv[F];
        const float* av = (const float*)acc;
        #pragma unroll
        for (int f = 0; f < F; f++) split2(av[f], hv[f], lv[f]);
        size_t base = (size_t)d * HCc + lane * F;
        #pragma unroll
        for (int q = 0; q < (F * 2) / 16; q++) {
            *(uint4*)&ohi[base + q * 8] = ((const uint4*)hv)[q];
            *(uint4*)&olo[base + q * 8] = ((const uint4*)lv)[q];
        }
    } else {
        float* op = &out[(size_t)d * HCc + lane * F];
        #pragma unroll
        for (int q = 0; q < V; q++) *(float4*)(op + q * 4) = acc[q];
    }
}

// ================================ launch =====================================
extern "C" void kernel_launch(void* const* d_in, const int* in_sizes, int n_in,
                              void* d_out, int out_size) {
    const float* x      = (const float*)d_in[0];
    const int*   ei     = (const int*)d_in[1];
    const float* W1     = (const float*)d_in[2];
    const float* a_src1 = (const float*)d_in[3];
    const float* a_dst1 = (const float*)d_in[4];
    const float* b1     = (const float*)d_in[5];
    const float* W2     = (const float*)d_in[6];
    const float* a_src2 = (const float*)d_in[7];
    const float* a_dst2 = (const float*)d_in[8];
    const float* b2     = (const float*)d_in[9];
    const float* W3     = (const float*)d_in[10];
    const float* a_src3 = (const float*)d_in[11];
    const float* a_dst3 = (const float*)d_in[12];
    const float* b3     = (const float*)d_in[13];
    float* out = (float*)d_out;

    const int n = NN;
    const int E = in_sizes[1] / 2;
    const int etot = E + n;

    float *hbuf, *als, *ald;
    __nv_bfloat16 *ahi, *alo, *wthi, *wtlo;
    int *deg, *rowstart, *cursor, *csr_src;
    cudaGetSymbolAddress((void**)&hbuf,     g_h);
    cudaGetSymbolAddress((void**)&ahi,      g_ahi);
    cudaGetSymbolAddress((void**)&alo,      g_alo);
    cudaGetSymbolAddress((void**)&wthi,     g_wthi);
    cudaGetSymbolAddress((void**)&wtlo,     g_wtlo);
    cudaGetSymbolAddress((void**)&als,      g_als);
    cudaGetSymbolAddress((void**)&ald,      g_ald);
    cudaGetSymbolAddress((void**)&deg,      g_deg);
    cudaGetSymbolAddress((void**)&rowstart, g_rowstart);
    cudaGetSymbolAddress((void**)&cursor,   g_cursor);
    cudaGetSymbolAddress((void**)&csr_src,  g_csr_src);

    // --- CSR build ---
    k_zero_deg<<<(n + 255) / 256, 256>>>(deg, n);
    k_count<<<(etot + 255) / 256, 256>>>(ei, E, n, deg);
    k_scan<<<1, 1024>>>(deg, rowstart, cursor, n);
    k_scatter<<<(etot + 255) / 256, 256>>>(ei, E, n, cursor, csr_src);

    const int warp_blocks = (n + 7) / 8;
    const int Mtiles = (n + 127) / 128;

    // --- layer 1: 128 -> 8x64 (concat) + ELU ---
    k_split_x<<<(n * IN_DIM + 255) / 256, 256>>>(x, ahi, alo, n * IN_DIM);
    k_split_wt<<<(IN_DIM * HC + 255) / 256, 256>>>(W1, wthi, wtlo, IN_DIM, HC);
    k_mma_gemm<<<dim3(HC / 128, Mtiles), 256>>>(ahi, alo, wthi, wtlo, hbuf, n, IN_DIM, HC);
    k_attn_logits<HEADS, HID><<<warp_blocks, 256>>>(hbuf, a_src1, a_dst1, als, ald, n);
    k_gat_aggregate<HEADS, HID, true, true><<<warp_blocks, 256>>>(
        hbuf, als, ald, rowstart, csr_src, b1, nullptr, ahi, alo, n);

    // --- layer 2: 512 -> 8x64 (concat) + ELU ---
    k_split_wt<<<(HC * HC + 255) / 256, 256>>>(W2, wthi, wtlo, HC, HC);
    k_mma_gemm<<<dim3(HC / 128, Mtiles), 256>>>(ahi, alo, wthi, wtlo, hbuf, n, HC, HC);
    k_attn_logits<HEADS, HID><<<warp_blocks, 256>>>(hbuf, a_src2, a_dst2, als, ald, n);
    k_gat_aggregate<HEADS, HID, true, true><<<warp_blocks, 256>>>(
        hbuf, als, ald, rowstart, csr_src, b2, nullptr, ahi, alo, n);

    // --- layer 3: 512 -> 128, heads=1, no concat ---
    k_split_wt<<<(HC * OUT_DIM + 255) / 256, 256>>>(W3, wthi, wtlo, HC, OUT_DIM);
    k_mma_gemm<<<dim3(OUT_DIM / 128, Mtiles), 256>>>(ahi, alo, wthi, wtlo, hbuf, n, HC, OUT_DIM);
    k_attn_logits<1, OUT_DIM><<<warp_blocks, 256>>>(hbuf, a_src3, a_dst3, als, ald, n);
    k_gat_aggregate<1, OUT_DIM, false, false><<<warp_blocks, 256>>>(
        hbuf, als, ald, rowstart, csr_src, b3, out, nullptr, nullptr, n);
}

// round 8
// speedup vs baseline: 1.6483x; 1.0325x over previous
#include <cuda_runtime.h>
#include <cuda_bf16.h>
#include <cstdint>
#include <math.h>

// Problem constants (fixed shapes)
#define NN      20000
#define EE      320000
#define ETOT    (EE + NN)
#define IN_DIM  128
#define HID     64
#define HEADS   8
#define HC      (HEADS * HID)    // 512
#define OUT_DIM 128
#define NEG_SLOPE 0.2f

// ============================ scratch buffers ================================
__device__ __align__(16) float         g_h   [(size_t)NN * HC];   // GEMM out (fp32)
__device__ __align__(16) __nv_bfloat16 g_ahi [(size_t)NN * HC];   // A hi (bf16)
__device__ __align__(16) __nv_bfloat16 g_alo [(size_t)NN * HC];   // A lo (bf16)
__device__ __align__(16) __nv_bfloat16 g_wthi[(size_t)HC * HC];   // W^T hi  [N][K]
__device__ __align__(16) __nv_bfloat16 g_wtlo[(size_t)HC * HC];   // W^T lo
__device__ __align__(16) float g_als[(size_t)NN * HEADS];
__device__ __align__(16) float g_ald[(size_t)NN * HEADS];
__device__ int g_deg     [NN];
__device__ int g_rowstart[NN + 1];
__device__ int g_cursor  [NN];
__device__ int g_csr_src [ETOT];

__device__ __forceinline__ void split2(float v, __nv_bfloat16& hi, __nv_bfloat16& lo) {
    hi = __float2bfloat16(v);
    lo = __float2bfloat16(v - __bfloat162float(hi));
}

__device__ __forceinline__ uint32_t smem_u32(const void* p) {
    uint32_t a;
    asm("{ .reg .u64 t; cvta.to.shared.u64 t, %1; cvt.u32.u64 %0, t; }"
        : "=r"(a) : "l"(p));
    return a;
}

// ================================ CSR build ==================================
__global__ void k_zero_deg(int* deg, int n) {
    int i = blockIdx.x * blockDim.x + threadIdx.x;
    if (i < n) deg[i] = 0;
}
__global__ void k_count(const int* __restrict__ ei, int E, int n, int* __restrict__ deg) {
    int e = blockIdx.x * blockDim.x + threadIdx.x;
    if (e >= E + n) return;
    int dst = (e < E) ? ei[E + e] : (e - E);
    atomicAdd(&deg[dst], 1);
}
__global__ void k_scan(const int* __restrict__ deg, int* __restrict__ rowstart,
                       int* __restrict__ cursor, int n) {
    __shared__ int sm[1024];
    int t = threadIdx.x;
    int CH = (n + 1023) >> 10;
    int lo = t * CH, hi = lo + CH; if (hi > n) hi = n;
    int loc = 0;
    for (int i = lo; i < hi; i++) loc += deg[i];
    sm[t] = loc;
    __syncthreads();
    for (int off = 1; off < 1024; off <<= 1) {
        int v = (t >= off) ? sm[t - off] : 0;
        __syncthreads();
        sm[t] += v;
        __syncthreads();
    }
    int run = sm[t] - loc;
    for (int i = lo; i < hi; i++) {
        rowstart[i] = run; cursor[i] = run; run += deg[i];
    }
    if (t == 1023) rowstart[n] = sm[1023];
}
__global__ void k_scatter(const int* __restrict__ ei, int E, int n,
                          int* __restrict__ cursor, int* __restrict__ csr_src) {
    int e = blockIdx.x * blockDim.x + threadIdx.x;
    if (e >= E + n) return;
    int src, dst;
    if (e < E) { src = ei[e]; dst = ei[E + e]; }
    else       { src = e - E; dst = e - E; }
    int pos = atomicAdd(&cursor[dst], 1);
    csr_src[pos] = src;
}

// ======================= fp32 -> bf16 hi/lo conversions ======================
__global__ void k_split_x(const float* __restrict__ x, __nv_bfloat16* __restrict__ hi,
                          __nv_bfloat16* __restrict__ lo, int total) {
    int i = blockIdx.x * blockDim.x + threadIdx.x;
    if (i >= total) return;
    split2(x[i], hi[i], lo[i]);
}
// W [K,N] fp32 -> Wt [N,K] bf16 hi/lo
__global__ void k_split_wt(const float* __restrict__ W, __nv_bfloat16* __restrict__ hi,
                           __nv_bfloat16* __restrict__ lo, int K, int N) {
    int i = blockIdx.x * blockDim.x + threadIdx.x;
    if (i >= K * N) return;
    int k = i / N, n = i % N;
    __nv_bfloat16 h, l;
    split2(W[i], h, l);
    hi[(size_t)n * K + k] = h;
    lo[(size_t)n * K + k] = l;
}

// =================== HMMA GEMM: C[M,N] = A[M,K] @ Wt[N,K]^T ==================
// bf16 hi/lo split, fp32 accumulate: D = Ah*Bh + Ah*Bl + Al*Bh.
// BM=128, BN=128, BK=32; 8 warps (2x4), 64x32 warp tiles.
// cp.async double-buffered smem pipeline (2 stages, 80 KB dynamic smem).

__device__ __forceinline__ void mma16816(float* d, const uint32_t* a, const uint32_t* b) {
    asm volatile(
        "mma.sync.aligned.m16n8k16.row.col.f32.bf16.bf16.f32 "
        "{%0,%1,%2,%3}, {%4,%5,%6,%7}, {%8,%9}, {%0,%1,%2,%3};"
        : "+f"(d[0]), "+f"(d[1]), "+f"(d[2]), "+f"(d[3])
        : "r"(a[0]), "r"(a[1]), "r"(a[2]), "r"(a[3]), "r"(b[0]), "r"(b[1]));
}
__device__ __forceinline__ void ldsm_x4(uint32_t* r, uint32_t addr) {
    asm volatile("ldmatrix.sync.aligned.m8n8.x4.shared.b16 {%0,%1,%2,%3}, [%4];"
                 : "=r"(r[0]), "=r"(r[1]), "=r"(r[2]), "=r"(r[3]) : "r"(addr));
}
__device__ __forceinline__ void ldsm_x2(uint32_t* r, uint32_t addr) {
    asm volatile("ldmatrix.sync.aligned.m8n8.x2.shared.b16 {%0,%1}, [%2];"
                 : "=r"(r[0]), "=r"(r[1]) : "r"(addr));
}
__device__ __forceinline__ void cp16(uint32_t dst, const void* src, int src_sz) {
    asm volatile("cp.async.cg.shared.global [%0], [%1], 16, %2;"
                 :: "r"(dst), "l"(src), "r"(src_sz));
}
#define CP_COMMIT() asm volatile("cp.async.commit_group;" ::: "memory")
#define CP_WAIT0()  asm volatile("cp.async.wait_group 0;" ::: "memory")

#define LDPAD 40                       // 80-byte row stride (16B-aligned, ldmatrix conflict-free)
#define ROWB  (LDPAD * 2)              // 80
#define ARR_BYTES (128 * ROWB)         // 10240
#define OFF_AH 0
#define OFF_AL (1 * ARR_BYTES)
#define OFF_BH (2 * ARR_BYTES)
#define OFF_BL (3 * ARR_BYTES)
#define STAGE_BYTES (4 * ARR_BYTES)    // 40960
#define GEMM_SMEM (2 * STAGE_BYTES)    // 81920

__global__ __launch_bounds__(256) void k_mma_gemm(
    const __nv_bfloat16* __restrict__ Ahi, const __nv_bfloat16* __restrict__ Alo,
    const __nv_bfloat16* __restrict__ Bhi, const __nv_bfloat16* __restrict__ Blo,
    float* __restrict__ C, int M, int K, int N)
{
    extern __shared__ __align__(16) char smem[];
    const uint32_t sb = smem_u32(smem);

    const int tid = threadIdx.x;
    const int wid = tid >> 5, lane = tid & 31;
    const int wm0 = (wid & 1) * 64;
    const int wn0 = (wid >> 1) * 32;
    const int row0 = blockIdx.y * 128, col0 = blockIdx.x * 128;

    float acc[4][4][4];
    #pragma unroll
    for (int i = 0; i < 4; i++)
        #pragma unroll
        for (int j = 0; j < 4; j++)
            #pragma unroll
            for (int q = 0; q < 4; q++) acc[i][j][q] = 0.f;

    // gmem staging: thread covers rows {ldr, ldr+64}, 16B column quantum ldq
    const int ldr = tid >> 2;              // 0..63
    const int ldq = (tid & 3) * 8;         // half offset (16B)
    const uint32_t sdst = (uint32_t)(ldr * ROWB + ldq * 2);

    // ldmatrix per-thread offsets (stage-relative)
    const int la = lane & 15;
    const uint32_t aoffs = (uint32_t)(((wm0 + la) * LDPAD + (lane >> 4) * 8) * 2);
    const uint32_t boffs = (uint32_t)(((wn0 + (la & 7)) * LDPAD + ((la >> 3) & 1) * 8) * 2);

    const int nch = K >> 5;

    // async fill of one stage for chunk ch
    auto issue = [&](int ch, int st) {
        const int k0 = ch << 5;
        const uint32_t stb = sb + st * STAGE_BYTES;
        #pragma unroll
        for (int i = 0; i < 2; i++) {
            const int r = ldr + i * 64;
            const uint32_t dd = sdst + (uint32_t)(i * 64 * ROWB);
            const int gr = row0 + r;
            const int ok = (gr < M) ? 16 : 0;
            const size_t ga = (size_t)(ok ? gr : 0) * K + k0 + ldq;
            cp16(stb + OFF_AH + dd, &Ahi[ga], ok);
            cp16(stb + OFF_AL + dd, &Alo[ga], ok);
            const size_t gb = (size_t)(col0 + r) * K + k0 + ldq;
            cp16(stb + OFF_BH + dd, &Bhi[gb], 16);
            cp16(stb + OFF_BL + dd, &Blo[gb], 16);
        }
        CP_COMMIT();
    };

    issue(0, 0);
    int st = 0;
    for (int ch = 0; ch < nch; ch++) {
        CP_WAIT0();          // stage 'st' data resident
        __syncthreads();     // all warps done with the other stage's compute
        if (ch + 1 < nch) issue(ch + 1, st ^ 1);

        const uint32_t stb = sb + st * STAGE_BYTES;
        const uint32_t aH = stb + OFF_AH + aoffs, aL = stb + OFF_AL + aoffs;
        const uint32_t bH = stb + OFF_BH + boffs, bL = stb + OFF_BL + boffs;
        #pragma unroll
        for (int stp = 0; stp < 2; stp++) {
            const uint32_t ko = stp * 32;   // 16 halves
            uint32_t Ah[4][4], Al[4][4], Bh[4][2], Bl[4][2];
            #pragma unroll
            for (int i = 0; i < 4; i++) {
                ldsm_x4(Ah[i], aH + ko + (uint32_t)(i * 16 * ROWB));
                ldsm_x4(Al[i], aL + ko + (uint32_t)(i * 16 * ROWB));
            }
            #pragma unroll
            for (int j = 0; j < 4; j++) {
                ldsm_x2(Bh[j], bH + ko + (uint32_t)(j * 8 * ROWB));
                ldsm_x2(Bl[j], bL + ko + (uint32_t)(j * 8 * ROWB));
            }
            #pragma unroll
            for (int i = 0; i < 4; i++)
                #pragma unroll
                for (int j = 0; j < 4; j++) {
                    mma16816(acc[i][j], Ah[i], Bh[j]);
                    mma16816(acc[i][j], Ah[i], Bl[j]);
                    mma16816(acc[i][j], Al[i], Bh[j]);
                }
        }
        st ^= 1;
    }

    // epilogue
    const int er = lane >> 2, ec = (lane & 3) * 2;
    #pragma unroll
    for (int i = 0; i < 4; i++) {
        #pragma unroll
        for (int j = 0; j < 4; j++) {
            int gr = row0 + wm0 + i * 16 + er;
            int gc = col0 + wn0 + j * 8 + ec;
            if (gr < M)
                *(float2*)&C[(size_t)gr * N + gc] = make_float2(acc[i][j][0], acc[i][j][1]);
            if (gr + 8 < M)
                *(float2*)&C[(size_t)(gr + 8) * N + gc] = make_float2(acc[i][j][2], acc[i][j][3]);
        }
    }
}

// ===================== per-node attention half-logits ========================
template<int H, int C>
__global__ __launch_bounds__(256) void k_attn_logits(
    const float* __restrict__ hfeat, const float* __restrict__ a_src,
    const float* __restrict__ a_dst, float* __restrict__ als,
    float* __restrict__ ald, int n)
{
    constexpr int HCc = H * C;
    constexpr int F = HCc / 32;
    constexpr int G = C / F;
    int warp = (blockIdx.x * blockDim.x + threadIdx.x) >> 5;
    int lane = threadIdx.x & 31;
    if (warp >= n) return;
    const float4* hp = (const float4*)&hfeat[(size_t)warp * HCc + lane * F];
    const float4* sp = (const float4*)&a_src[lane * F];
    const float4* dp = (const float4*)&a_dst[lane * F];
    float s1 = 0.f, s2 = 0.f;
    #pragma unroll
    for (int q = 0; q < F / 4; q++) {
        float4 v = hp[q], w1 = sp[q], w2 = dp[q];
        s1 += v.x * w1.x + v.y * w1.y + v.z * w1.z + v.w * w1.w;
        s2 += v.x * w2.x + v.y * w2.y + v.z * w2.z + v.w * w2.w;
    }
    #pragma unroll
    for (int o = 1; o < G; o <<= 1) {
        s1 += __shfl_xor_sync(0xffffffffu, s1, o);
        s2 += __shfl_xor_sync(0xffffffffu, s2, o);
    }
    if ((lane % G) == 0) {
        int hd = lane / G;
        als[(size_t)warp * H + hd] = s1;
        ald[(size_t)warp * H + hd] = s2;
    }
}

// ============ fused segment softmax + weighted aggregate (warp/node) =========
template<int H, int C, bool ELU, bool SPLIT>
__global__ __launch_bounds__(256) void k_gat_aggregate(
    const float* __restrict__ hfeat, const float* __restrict__ als,
    const float* __restrict__ ald, const int* __restrict__ rowstart,
    const int* __restrict__ csr_src, const float* __restrict__ bias,
    float* __restrict__ out, __nv_bfloat16* __restrict__ ohi,
    __nv_bfloat16* __restrict__ olo, int n)
{
    constexpr int HCc = H * C;
    constexpr int F = HCc / 32;
    constexpr int V = F / 4;
    int warp = (blockIdx.x * blockDim.x + threadIdx.x) >> 5;
    int lane = threadIdx.x & 31;
    if (warp >= n) return;
    int d = warp;
    int start = rowstart[d], end = rowstart[d + 1];

    float al_d[H];
    #pragma unroll
    for (int h = 0; h < H; h++) al_d[h] = ald[(size_t)d * H + h];

    float mx[H];
    #pragma unroll
    for (int h = 0; h < H; h++) mx[h] = -1e30f;
    for (int j = start + lane; j < end; j += 32) {
        int s = csr_src[j];
        #pragma unroll
        for (int h = 0; h < H; h++) {
            float v = als[(size_t)s * H + h] + al_d[h];
            v = (v > 0.f) ? v : NEG_SLOPE * v;
            mx[h] = fmaxf(mx[h], v);
        }
    }
    #pragma unroll
    for (int h = 0; h < H; h++)
        #pragma unroll
        for (int o = 16; o > 0; o >>= 1)
            mx[h] = fmaxf(mx[h], __shfl_xor_sync(0xffffffffu, mx[h], o));

    float smv[H];
    #pragma unroll
    for (int h = 0; h < H; h++) smv[h] = 0.f;
    for (int j = start + lane; j < end; j += 32) {
        int s = csr_src[j];
        #pragma unroll
        for (int h = 0; h < H; h++) {
            float v = als[(size_t)s * H + h] + al_d[h];
            v = (v > 0.f) ? v : NEG_SLOPE * v;
            smv[h] += __expf(v - mx[h]);
        }
    }
    #pragma unroll
    for (int h = 0; h < H; h++)
        #pragma unroll
        for (int o = 16; o > 0; o >>= 1)
            smv[h] += __shfl_xor_sync(0xffffffffu, smv[h], o);

    const int myhead = (lane * F) / C;
    float my_ald = al_d[myhead];
    float my_mx  = mx[myhead];
    float my_inv = 1.0f / (smv[myhead] + 1e-16f);

    float4 acc[V];
    #pragma unroll
    for (int q = 0; q < V; q++) acc[q] = make_float4(0.f, 0.f, 0.f, 0.f);
    for (int j = start; j < end; j++) {
        int s = csr_src[j];
        float v = als[(size_t)s * H + myhead] + my_ald;
        v = (v > 0.f) ? v : NEG_SLOPE * v;
        float alpha = __expf(v - my_mx) * my_inv;
        const float4* hp = (const float4*)&hfeat[(size_t)s * HCc + lane * F];
        #pragma unroll
        for (int q = 0; q < V; q++) {
            float4 t = hp[q];
            acc[q].x += alpha * t.x; acc[q].y += alpha * t.y;
            acc[q].z += alpha * t.z; acc[q].w += alpha * t.w;
        }
    }

    const float4* bp = (const float4*)&bias[lane * F];
    #pragma unroll
    for (int q = 0; q < V; q++) {
        float4 b = bp[q];
        acc[q].x += b.x; acc[q].y += b.y; acc[q].z += b.z; acc[q].w += b.w;
        if (ELU) {
            acc[q].x = (acc[q].x > 0.f) ? acc[q].x : (__expf(acc[q].x) - 1.f);
            acc[q].y = (acc[q].y > 0.f) ? acc[q].y : (__expf(acc[q].y) - 1.f);
            acc[q].z = (acc[q].z > 0.f) ? acc[q].z : (__expf(acc[q].z) - 1.f);
            acc[q].w = (acc[q].w > 0.f) ? acc[q].w : (__expf(acc[q].w) - 1.f);
        }
    }

    if (SPLIT) {
        __nv_bfloat16 hv[F], lv[F];
        const float* av = (const float*)acc;
        #pragma unroll
        for (int f = 0; f < F; f++) split2(av[f], hv[f], lv[f]);
        size_t base = (size_t)d * HCc + lane * F;
        #pragma unroll
        for (int q = 0; q < (F * 2) / 16; q++) {
            *(uint4*)&ohi[base + q * 8] = ((const uint4*)hv)[q];
            *(uint4*)&olo[base + q * 8] = ((const uint4*)lv)[q];
        }
    } else {
        float* op = &out[(size_t)d * HCc + lane * F];
        #pragma unroll
        for (int q = 0; q < V; q++) *(float4*)(op + q * 4) = acc[q];
    }
}

// ================================ launch =====================================
extern "C" void kernel_launch(void* const* d_in, const int* in_sizes, int n_in,
                              void* d_out, int out_size) {
    const float* x      = (const float*)d_in[0];
    const int*   ei     = (const int*)d_in[1];
    const float* W1     = (const float*)d_in[2];
    const float* a_src1 = (const float*)d_in[3];
    const float* a_dst1 = (const float*)d_in[4];
    const float* b1     = (const float*)d_in[5];
    const float* W2     = (const float*)d_in[6];
    const float* a_src2 = (const float*)d_in[7];
    const float* a_dst2 = (const float*)d_in[8];
    const float* b2     = (const float*)d_in[9];
    const float* W3     = (const float*)d_in[10];
    const float* a_src3 = (const float*)d_in[11];
    const float* a_dst3 = (const float*)d_in[12];
    const float* b3     = (const float*)d_in[13];
    float* out = (float*)d_out;

    const int n = NN;
    const int E = in_sizes[1] / 2;
    const int etot = E + n;

    float *hbuf, *als, *ald;
    __nv_bfloat16 *ahi, *alo, *wthi, *wtlo;
    int *deg, *rowstart, *cursor, *csr_src;
    cudaGetSymbolAddress((void**)&hbuf,     g_h);
    cudaGetSymbolAddress((void**)&ahi,      g_ahi);
    cudaGetSymbolAddress((void**)&alo,      g_alo);
    cudaGetSymbolAddress((void**)&wthi,     g_wthi);
    cudaGetSymbolAddress((void**)&wtlo,     g_wtlo);
    cudaGetSymbolAddress((void**)&als,      g_als);
    cudaGetSymbolAddress((void**)&ald,      g_ald);
    cudaGetSymbolAddress((void**)&deg,      g_deg);
    cudaGetSymbolAddress((void**)&rowstart, g_rowstart);
    cudaGetSymbolAddress((void**)&cursor,   g_cursor);
    cudaGetSymbolAddress((void**)&csr_src,  g_csr_src);

    cudaFuncSetAttribute(k_mma_gemm, cudaFuncAttributeMaxDynamicSharedMemorySize, GEMM_SMEM);

    // --- CSR build ---
    k_zero_deg<<<(n + 255) / 256, 256>>>(deg, n);
    k_count<<<(etot + 255) / 256, 256>>>(ei, E, n, deg);
    k_scan<<<1, 1024>>>(deg, rowstart, cursor, n);
    k_scatter<<<(etot + 255) / 256, 256>>>(ei, E, n, cursor, csr_src);

    const int warp_blocks = (n + 7) / 8;
    const int Mtiles = (n + 127) / 128;

    // --- layer 1: 128 -> 8x64 (concat) + ELU ---
    k_split_x<<<(n * IN_DIM + 255) / 256, 256>>>(x, ahi, alo, n * IN_DIM);
    k_split_wt<<<(IN_DIM * HC + 255) / 256, 256>>>(W1, wthi, wtlo, IN_DIM, HC);
    k_mma_gemm<<<dim3(HC / 128, Mtiles), 256, GEMM_SMEM>>>(ahi, alo, wthi, wtlo, hbuf, n, IN_DIM, HC);
    k_attn_logits<HEADS, HID><<<warp_blocks, 256>>>(hbuf, a_src1, a_dst1, als, ald, n);
    k_gat_aggregate<HEADS, HID, true, true><<<warp_blocks, 256>>>(
        hbuf, als, ald, rowstart, csr_src, b1, nullptr, ahi, alo, n);

    // --- layer 2: 512 -> 8x64 (concat) + ELU ---
    k_split_wt<<<(HC * HC + 255) / 256, 256>>>(W2, wthi, wtlo, HC, HC);
    k_mma_gemm<<<dim3(HC / 128, Mtiles), 256, GEMM_SMEM>>>(ahi, alo, wthi, wtlo, hbuf, n, HC, HC);
    k_attn_logits<HEADS, HID><<<warp_blocks, 256>>>(hbuf, a_src2, a_dst2, als, ald, n);
    k_gat_aggregate<HEADS, HID, true, true><<<warp_blocks, 256>>>(
        hbuf, als, ald, rowstart, csr_src, b2, nullptr, ahi, alo, n);

    // --- layer 3: 512 -> 128, heads=1, no concat ---
    k_split_wt<<<(HC * OUT_DIM + 255) / 256, 256>>>(W3, wthi, wtlo, HC, OUT_DIM);
    k_mma_gemm<<<dim3(OUT_DIM / 128, Mtiles), 256, GEMM_SMEM>>>(ahi, alo, wthi, wtlo, hbuf, n, HC, OUT_DIM);
    k_attn_logits<1, OUT_DIM><<<warp_blocks, 256>>>(hbuf, a_src3, a_dst3, als, ald, n);
    k_gat_aggregate<1, OUT_DIM, false, false><<<warp_blocks, 256>>>(
        hbuf, als, ald, rowstart, csr_src, b3, out, nullptr, nullptr, n);
}

// round 12
// speedup vs baseline: 1.7419x; 1.0567x over previous
#include <cuda_runtime.h>
#include <cuda_bf16.h>
#include <cstdint>
#include <math.h>

// Problem constants (fixed shapes)
#define NN      20000
#define EE      320000
#define ETOT    (EE + NN)
#define IN_DIM  128
#define HID     64
#define HEADS   8
#define HC      (HEADS * HID)    // 512
#define OUT_DIM 128
#define NEG_SLOPE 0.2f

// ============================ scratch buffers ================================
__device__ __align__(16) float         g_h   [(size_t)NN * HC];   // GEMM out (fp32)
__device__ __align__(16) __nv_bfloat16 g_ahi [(size_t)NN * HC];   // A hi (bf16)
__device__ __align__(16) __nv_bfloat16 g_alo [(size_t)NN * HC];   // A lo (bf16)
__device__ __align__(16) __nv_bfloat16 g_wthi[(size_t)HC * HC];   // W^T hi  [N][K]
__device__ __align__(16) __nv_bfloat16 g_wtlo[(size_t)HC * HC];   // W^T lo
__device__ __align__(16) float g_als[(size_t)NN * HEADS];
__device__ __align__(16) float g_ald[(size_t)NN * HEADS];
__device__ __align__(16) float g_exv[(size_t)ETOT * HEADS];       // per-edge exp(logit)
__device__ int g_deg     [NN];
__device__ int g_rowstart[NN + 1];
__device__ int g_cursor  [NN];
__device__ int g_csr_src [ETOT];
__device__ int g_csr_dst [ETOT];

__device__ __forceinline__ void split2(float v, __nv_bfloat16& hi, __nv_bfloat16& lo) {
    hi = __float2bfloat16(v);
    lo = __float2bfloat16(v - __bfloat162float(hi));
}

__device__ __forceinline__ uint32_t smem_u32(const void* p) {
    uint32_t a;
    asm("{ .reg .u64 t; cvta.to.shared.u64 t, %1; cvt.u32.u64 %0, t; }"
        : "=r"(a) : "l"(p));
    return a;
}

// ================================ CSR build ==================================
__global__ void k_zero_deg(int* deg, int n) {
    int i = blockIdx.x * blockDim.x + threadIdx.x;
    if (i < n) deg[i] = 0;
}
__global__ void k_count(const int* __restrict__ ei, int E, int n, int* __restrict__ deg) {
    int e = blockIdx.x * blockDim.x + threadIdx.x;
    if (e >= E + n) return;
    int dst = (e < E) ? ei[E + e] : (e - E);
    atomicAdd(&deg[dst], 1);
}
__global__ void k_scan(const int* __restrict__ deg, int* __restrict__ rowstart,
                       int* __restrict__ cursor, int n) {
    __shared__ int sm[1024];
    int t = threadIdx.x;
    int CH = (n + 1023) >> 10;
    int lo = t * CH, hi = lo + CH; if (hi > n) hi = n;
    int loc = 0;
    for (int i = lo; i < hi; i++) loc += deg[i];
    sm[t] = loc;
    __syncthreads();
    for (int off = 1; off < 1024; off <<= 1) {
        int v = (t >= off) ? sm[t - off] : 0;
        __syncthreads();
        sm[t] += v;
        __syncthreads();
    }
    int run = sm[t] - loc;
    for (int i = lo; i < hi; i++) {
        rowstart[i] = run; cursor[i] = run; run += deg[i];
    }
    if (t == 1023) rowstart[n] = sm[1023];
}
__global__ void k_scatter(const int* __restrict__ ei, int E, int n,
                          int* __restrict__ cursor, int* __restrict__ csr_src,
                          int* __restrict__ csr_dst) {
    int e = blockIdx.x * blockDim.x + threadIdx.x;
    if (e >= E + n) return;
    int src, dst;
    if (e < E) { src = ei[e]; dst = ei[E + e]; }
    else       { src = e - E; dst = e - E; }
    int pos = atomicAdd(&cursor[dst], 1);
    csr_src[pos] = src;
    csr_dst[pos] = dst;
}

// ======================= fp32 -> bf16 hi/lo conversions ======================
__global__ void k_split_x(const float* __restrict__ x, __nv_bfloat16* __restrict__ hi,
                          __nv_bfloat16* __restrict__ lo, int total) {
    int i = blockIdx.x * blockDim.x + threadIdx.x;
    if (i >= total) return;
    split2(x[i], hi[i], lo[i]);
}
// W [K,N] fp32 -> Wt [N,K] bf16 hi/lo
__global__ void k_split_wt(const float* __restrict__ W, __nv_bfloat16* __restrict__ hi,
                           __nv_bfloat16* __restrict__ lo, int K, int N) {
    int i = blockIdx.x * blockDim.x + threadIdx.x;
    if (i >= K * N) return;
    int k = i / N, n = i % N;
    __nv_bfloat16 h, l;
    split2(W[i], h, l);
    hi[(size_t)n * K + k] = h;
    lo[(size_t)n * K + k] = l;
}

// =================== HMMA GEMM: C[M,N] = A[M,K] @ Wt[N,K]^T ==================
// bf16 hi/lo split, fp32 accumulate: D = Ah*Bh + Ah*Bl + Al*Bh.
// BM=128, BN=128, BK=32; 8 warps (2x4), 64x32 warp tiles; cp.async 2-stage.

__device__ __forceinline__ void mma16816(float* d, const uint32_t* a, const uint32_t* b) {
    asm volatile(
        "mma.sync.aligned.m16n8k16.row.col.f32.bf16.bf16.f32 "
        "{%0,%1,%2,%3}, {%4,%5,%6,%7}, {%8,%9}, {%0,%1,%2,%3};"
        : "+f"(d[0]), "+f"(d[1]), "+f"(d[2]), "+f"(d[3])
        : "r"(a[0]), "r"(a[1]), "r"(a[2]), "r"(a[3]), "r"(b[0]), "r"(b[1]));
}
__device__ __forceinline__ void ldsm_x4(uint32_t* r, uint32_t addr) {
    asm volatile("ldmatrix.sync.aligned.m8n8.x4.shared.b16 {%0,%1,%2,%3}, [%4];"
                 : "=r"(r[0]), "=r"(r[1]), "=r"(r[2]), "=r"(r[3]) : "r"(addr));
}
__device__ __forceinline__ void ldsm_x2(uint32_t* r, uint32_t addr) {
    asm volatile("ldmatrix.sync.aligned.m8n8.x2.shared.b16 {%0,%1}, [%2];"
                 : "=r"(r[0]), "=r"(r[1]) : "r"(addr));
}
__device__ __forceinline__ void cp16(uint32_t dst, const void* src, int src_sz) {
    asm volatile("cp.async.cg.shared.global [%0], [%1], 16, %2;"
                 :: "r"(dst), "l"(src), "r"(src_sz));
}
#define CP_COMMIT() asm volatile("cp.async.commit_group;" ::: "memory")
#define CP_WAIT0()  asm volatile("cp.async.wait_group 0;" ::: "memory")

#define LDPAD 40
#define ROWB  (LDPAD * 2)              // 80
#define ARR_BYTES (128 * ROWB)         // 10240
#define OFF_AH 0
#define OFF_AL (1 * ARR_BYTES)
#define OFF_BH (2 * ARR_BYTES)
#define OFF_BL (3 * ARR_BYTES)
#define STAGE_BYTES (4 * ARR_BYTES)    // 40960
#define GEMM_SMEM (2 * STAGE_BYTES)    // 81920

__global__ __launch_bounds__(256) void k_mma_gemm(
    const __nv_bfloat16* __restrict__ Ahi, const __nv_bfloat16* __restrict__ Alo,
    const __nv_bfloat16* __restrict__ Bhi, const __nv_bfloat16* __restrict__ Blo,
    float* __restrict__ C, int M, int K, int N)
{
    extern __shared__ __align__(16) char smem[];
    const uint32_t sb = smem_u32(smem);

    const int tid = threadIdx.x;
    const int wid = tid >> 5, lane = tid & 31;
    const int wm0 = (wid & 1) * 64;
    const int wn0 = (wid >> 1) * 32;
    const int row0 = blockIdx.y * 128, col0 = blockIdx.x * 128;

    float acc[4][4][4];
    #pragma unroll
    for (int i = 0; i < 4; i++)
        #pragma unroll
        for (int j = 0; j < 4; j++)
            #pragma unroll
            for (int q = 0; q < 4; q++) acc[i][j][q] = 0.f;

    const int ldr = tid >> 2;
    const int ldq = (tid & 3) * 8;
    const uint32_t sdst = (uint32_t)(ldr * ROWB + ldq * 2);

    const int la = lane & 15;
    const uint32_t aoffs = (uint32_t)(((wm0 + la) * LDPAD + (lane >> 4) * 8) * 2);
    const uint32_t boffs = (uint32_t)(((wn0 + (la & 7)) * LDPAD + ((la >> 3) & 1) * 8) * 2);

    const int nch = K >> 5;

    auto issue = [&](int ch, int st) {
        const int k0 = ch << 5;
        const uint32_t stb = sb + st * STAGE_BYTES;
        #pragma unroll
        for (int i = 0; i < 2; i++) {
            const int r = ldr + i * 64;
            const uint32_t dd = sdst + (uint32_t)(i * 64 * ROWB);
            const int gr = row0 + r;
            const int ok = (gr < M) ? 16 : 0;
            const size_t ga = (size_t)(ok ? gr : 0) * K + k0 + ldq;
            cp16(stb + OFF_AH + dd, &Ahi[ga], ok);
            cp16(stb + OFF_AL + dd, &Alo[ga], ok);
            const size_t gb = (size_t)(col0 + r) * K + k0 + ldq;
            cp16(stb + OFF_BH + dd, &Bhi[gb], 16);
            cp16(stb + OFF_BL + dd, &Blo[gb], 16);
        }
        CP_COMMIT();
    };

    issue(0, 0);
    int st = 0;
    for (int ch = 0; ch < nch; ch++) {
        CP_WAIT0();
        __syncthreads();
        if (ch + 1 < nch) issue(ch + 1, st ^ 1);

        const uint32_t stb = sb + st * STAGE_BYTES;
        const uint32_t aH = stb + OFF_AH + aoffs, aL = stb + OFF_AL + aoffs;
        const uint32_t bH = stb + OFF_BH + boffs, bL = stb + OFF_BL + boffs;
        #pragma unroll
        for (int stp = 0; stp < 2; stp++) {
            const uint32_t ko = stp * 32;
            uint32_t Ah[4][4], Al[4][4], Bh[4][2], Bl[4][2];
            #pragma unroll
            for (int i = 0; i < 4; i++) {
                ldsm_x4(Ah[i], aH + ko + (uint32_t)(i * 16 * ROWB));
                ldsm_x4(Al[i], aL + ko + (uint32_t)(i * 16 * ROWB));
            }
            #pragma unroll
            for (int j = 0; j < 4; j++) {
                ldsm_x2(Bh[j], bH + ko + (uint32_t)(j * 8 * ROWB));
                ldsm_x2(Bl[j], bL + ko + (uint32_t)(j * 8 * ROWB));
            }
            #pragma unroll
            for (int i = 0; i < 4; i++)
                #pragma unroll
                for (int j = 0; j < 4; j++) {
                    mma16816(acc[i][j], Ah[i], Bh[j]);
                    mma16816(acc[i][j], Ah[i], Bl[j]);
                    mma16816(acc[i][j], Al[i], Bh[j]);
                }
        }
        st ^= 1;
    }

    const int er = lane >> 2, ec = (lane & 3) * 2;
    #pragma unroll
    for (int i = 0; i < 4; i++) {
        #pragma unroll
        for (int j = 0; j < 4; j++) {
            int gr = row0 + wm0 + i * 16 + er;
            int gc = col0 + wn0 + j * 8 + ec;
            if (gr < M)
                *(float2*)&C[(size_t)gr * N + gc] = make_float2(acc[i][j][0], acc[i][j][1]);
            if (gr + 8 < M)
                *(float2*)&C[(size_t)(gr + 8) * N + gc] = make_float2(acc[i][j][2], acc[i][j][3]);
        }
    }
}

// ===================== per-node attention half-logits ========================
template<int H, int C>
__global__ __launch_bounds__(256) void k_attn_logits(
    const float* __restrict__ hfeat, const float* __restrict__ a_src,
    const float* __restrict__ a_dst, float* __restrict__ als,
    float* __restrict__ ald, int n)
{
    constexpr int HCc = H * C;
    constexpr int F = HCc / 32;
    constexpr int G = C / F;
    int warp = (blockIdx.x * blockDim.x + threadIdx.x) >> 5;
    int lane = threadIdx.x & 31;
    if (warp >= n) return;
    const float4* hp = (const float4*)&hfeat[(size_t)warp * HCc + lane * F];
    const float4* sp = (const float4*)&a_src[lane * F];
    const float4* dp = (const float4*)&a_dst[lane * F];
    float s1 = 0.f, s2 = 0.f;
    #pragma unroll
    for (int q = 0; q < F / 4; q++) {
        float4 v = hp[q], w1 = sp[q], w2 = dp[q];
        s1 += v.x * w1.x + v.y * w1.y + v.z * w1.z + v.w * w1.w;
        s2 += v.x * w2.x + v.y * w2.y + v.z * w2.z + v.w * w2.w;
    }
    #pragma unroll
    for (int o = 1; o < G; o <<= 1) {
        s1 += __shfl_xor_sync(0xffffffffu, s1, o);
        s2 += __shfl_xor_sync(0xffffffffu, s2, o);
    }
    if ((lane % G) == 0) {
        int hd = lane / G;
        als[(size_t)warp * H + hd] = s1;
        ald[(size_t)warp * H + hd] = s2;
    }
}

// ============== edge-parallel exp(leaky(logit)) — one exp per (edge,head) ====
// No max-subtraction: logits are O(few); exp cannot overflow fp32; the alpha
// ratios are mathematically identical to the max-subtracted reference.
template<int H>
__global__ __launch_bounds__(256) void k_edge_exp(
    const float* __restrict__ als, const float* __restrict__ ald,
    const int* __restrict__ csr_src, const int* __restrict__ csr_dst,
    float* __restrict__ exv, int etot)
{
    int j = blockIdx.x * blockDim.x + threadIdx.x;
    if (j >= etot) return;
    int s = csr_src[j], d = csr_dst[j];
    if (H == 8) {
        const float4* as = (const float4*)&als[(size_t)s * 8];
        const float4* ad = (const float4*)&ald[(size_t)d * 8];
        float4* ev = (float4*)&exv[(size_t)j * 8];
        #pragma unroll
        for (int q = 0; q < 2; q++) {
            float4 a = as[q], b = ad[q], r;
            float v;
            v = a.x + b.x; v = (v > 0.f) ? v : NEG_SLOPE * v; r.x = __expf(v);
            v = a.y + b.y; v = (v > 0.f) ? v : NEG_SLOPE * v; r.y = __expf(v);
            v = a.z + b.z; v = (v > 0.f) ? v : NEG_SLOPE * v; r.z = __expf(v);
            v = a.w + b.w; v = (v > 0.f) ? v : NEG_SLOPE * v; r.w = __expf(v);
            ev[q] = r;
        }
    } else {
        float v = als[s] + ald[d];
        v = (v > 0.f) ? v : NEG_SLOPE * v;
        exv[j] = __expf(v);
    }
}

// ======= single-pass weighted aggregate: acc = Σ ev·h, normalize at end ======
template<int H, int C, bool ELU, bool SPLIT>
__global__ __launch_bounds__(256) void k_gat_aggregate(
    const float* __restrict__ hfeat, const float* __restrict__ exv,
    const int* __restrict__ rowstart, const int* __restrict__ csr_src,
    const float* __restrict__ bias, float* __restrict__ out,
    __nv_bfloat16* __restrict__ ohi, __nv_bfloat16* __restrict__ olo, int n)
{
    constexpr int HCc = H * C;
    constexpr int F = HCc / 32;
    constexpr int V = F / 4;
    int warp = (blockIdx.x * blockDim.x + threadIdx.x) >> 5;
    int lane = threadIdx.x & 31;
    if (warp >= n) return;
    const int d = warp;
    const int start = rowstart[d], end = rowstart[d + 1];
    const int myhead = (lane * F) / C;

    float den = 0.f;
    float4 acc[V];
    #pragma unroll
    for (int q = 0; q < V; q++) acc[q] = make_float4(0.f, 0.f, 0.f, 0.f);

    for (int j = start; j < end; j++) {
        int s = csr_src[j];
        float ev = exv[(size_t)j * H + myhead];
        den += ev;
        const float4* hp = (const float4*)&hfeat[(size_t)s * HCc + lane * F];
        #pragma unroll
        for (int q = 0; q < V; q++) {
            float4 t = hp[q];
            acc[q].x += ev * t.x; acc[q].y += ev * t.y;
            acc[q].z += ev * t.z; acc[q].w += ev * t.w;
        }
    }

    const float inv = 1.0f / den;   // den >= exp(self-loop logit) > 0
    const float4* bp = (const float4*)&bias[lane * F];
    #pragma unroll
    for (int q = 0; q < V; q++) {
        float4 b = bp[q];
        acc[q].x = acc[q].x * inv + b.x;
        acc[q].y = acc[q].y * inv + b.y;
        acc[q].z = acc[q].z * inv + b.z;
        acc[q].w = acc[q].w * inv + b.w;
        if (ELU) {
            acc[q].x = (acc[q].x > 0.f) ? acc[q].x : (__expf(acc[q].x) - 1.f);
            acc[q].y = (acc[q].y > 0.f) ? acc[q].y : (__expf(acc[q].y) - 1.f);
            acc[q].z = (acc[q].z > 0.f) ? acc[q].z : (__expf(acc[q].z) - 1.f);
            acc[q].w = (acc[q].w > 0.f) ? acc[q].w : (__expf(acc[q].w) - 1.f);
        }
    }

    if (SPLIT) {
        __nv_bfloat16 hv[F], lv[F];
        const float* av = (const float*)acc;
        #pragma unroll
        for (int f = 0; f < F; f++) split2(av[f], hv[f], lv[f]);
        size_t base = (size_t)d * HCc + lane * F;
        #pragma unroll
        for (int q = 0; q < (F * 2) / 16; q++) {
            *(uint4*)&ohi[base + q * 8] = ((const uint4*)hv)[q];
            *(uint4*)&olo[base + q * 8] = ((const uint4*)lv)[q];
        }
    } else {
        float* op = &out[(size_t)d * HCc + lane * F];
        #pragma unroll
        for (int q = 0; q < V; q++) *(float4*)(op + q * 4) = acc[q];
    }
}

// ================================ launch =====================================
extern "C" void kernel_launch(void* const* d_in, const int* in_sizes, int n_in,
                              void* d_out, int out_size) {
    const float* x      = (const float*)d_in[0];
    const int*   ei     = (const int*)d_in[1];
    const float* W1     = (const float*)d_in[2];
    const float* a_src1 = (const float*)d_in[3];
    const float* a_dst1 = (const float*)d_in[4];
    const float* b1     = (const float*)d_in[5];
    const float* W2     = (const float*)d_in[6];
    const float* a_src2 = (const float*)d_in[7];
    const float* a_dst2 = (const float*)d_in[8];
    const float* b2     = (const float*)d_in[9];
    const float* W3     = (const float*)d_in[10];
    const float* a_src3 = (const float*)d_in[11];
    const float* a_dst3 = (const float*)d_in[12];
    const float* b3     = (const float*)d_in[13];
    float* out = (float*)d_out;

    const int n = NN;
    const int E = in_sizes[1] / 2;
    const int etot = E + n;

    float *hbuf, *als, *ald, *exv;
    __nv_bfloat16 *ahi, *alo, *wthi, *wtlo;
    int *deg, *rowstart, *cursor, *csr_src, *csr_dst;
    cudaGetSymbolAddress((void**)&hbuf,     g_h);
    cudaGetSymbolAddress((void**)&ahi,      g_ahi);
    cudaGetSymbolAddress((void**)&alo,      g_alo);
    cudaGetSymbolAddress((void**)&wthi,     g_wthi);
    cudaGetSymbolAddress((void**)&wtlo,     g_wtlo);
    cudaGetSymbolAddress((void**)&als,      g_als);
    cudaGetSymbolAddress((void**)&ald,      g_ald);
    cudaGetSymbolAddress((void**)&exv,      g_exv);
    cudaGetSymbolAddress((void**)&deg,      g_deg);
    cudaGetSymbolAddress((void**)&rowstart, g_rowstart);
    cudaGetSymbolAddress((void**)&cursor,   g_cursor);
    cudaGetSymbolAddress((void**)&csr_src,  g_csr_src);
    cudaGetSymbolAddress((void**)&csr_dst,  g_csr_dst);

    cudaFuncSetAttribute(k_mma_gemm, cudaFuncAttributeMaxDynamicSharedMemorySize, GEMM_SMEM);

    const int warp_blocks = (n + 7) / 8;
    const int edge_blocks = (etot + 255) / 256;
    const int Mtiles = (n + 127) / 128;

    // launches 1-4: zero, split_x, split_wt1, gemm1  (gemm lands in ncu's slot)
    k_zero_deg<<<(n + 255) / 256, 256>>>(deg, n);
    k_split_x<<<(n * IN_DIM + 255) / 256, 256>>>(x, ahi, alo, n * IN_DIM);
    k_split_wt<<<(IN_DIM * HC + 255) / 256, 256>>>(W1, wthi, wtlo, IN_DIM, HC);
    k_mma_gemm<<<dim3(HC / 128, Mtiles), 256, GEMM_SMEM>>>(ahi, alo, wthi, wtlo, hbuf, n, IN_DIM, HC);

    // CSR build
    k_count<<<edge_blocks, 256>>>(ei, E, n, deg);
    k_scan<<<1, 1024>>>(deg, rowstart, cursor, n);
    k_scatter<<<edge_blocks, 256>>>(ei, E, n, cursor, csr_src, csr_dst);

    // --- layer 1 attention + aggregate ---
    k_attn_logits<HEADS, HID><<<warp_blocks, 256>>>(hbuf, a_src1, a_dst1, als, ald, n);
    k_edge_exp<HEADS><<<edge_blocks, 256>>>(als, ald, csr_src, csr_dst, exv, etot);
    k_gat_aggregate<HEADS, HID, true, true><<<warp_blocks, 256>>>(
        hbuf, exv, rowstart, csr_src, b1, nullptr, ahi, alo, n);

    // --- layer 2 ---
    k_split_wt<<<(HC * HC + 255) / 256, 256>>>(W2, wthi, wtlo, HC, HC);
    k_mma_gemm<<<dim3(HC / 128, Mtiles), 256, GEMM_SMEM>>>(ahi, alo, wthi, wtlo, hbuf, n, HC, HC);
    k_attn_logits<HEADS, HID><<<warp_blocks, 256>>>(hbuf, a_src2, a_dst2, als, ald, n);
    k_edge_exp<HEADS><<<edge_blocks, 256>>>(als, ald, csr_src, csr_dst, exv, etot);
    k_gat_aggregate<HEADS, HID, true, true><<<warp_blocks, 256>>>(
        hbuf, exv, rowstart, csr_src, b2, nullptr, ahi, alo, n);

    // --- layer 3: 512 -> 128, heads=1, no concat ---
    k_split_wt<<<(HC * OUT_DIM + 255) / 256, 256>>>(W3, wthi, wtlo, HC, OUT_DIM);
    k_mma_gemm<<<dim3(OUT_DIM / 128, Mtiles), 256, GEMM_SMEM>>>(ahi, alo, wthi, wtlo, hbuf, n, HC, OUT_DIM);
    k_attn_logits<1, OUT_DIM><<<warp_blocks, 256>>>(hbuf, a_src3, a_dst3, als, ald, n);
    k_edge_exp<1><<<edge_blocks, 256>>>(als, ald, csr_src, csr_dst, exv, etot);
    k_gat_aggregate<1, OUT_DIM, false, false><<<warp_blocks, 256>>>(
        hbuf, exv, rowstart, csr_src, b3, out, nullptr, nullptr, n);
}

// round 13
// speedup vs baseline: 1.9619x; 1.1263x over previous
#include <cuda_runtime.h>
#include <cuda_fp16.h>
#include <cstdint>
#include <math.h>

// Problem constants (fixed shapes)
#define NN      20000
#define EE      320000
#define ETOT    (EE + NN)
#define IN_DIM  128
#define HID     64
#define HEADS   8
#define HC      (HEADS * HID)    // 512
#define OUT_DIM 128
#define NEG_SLOPE 0.2f

// ============================ scratch buffers ================================
__device__ __align__(16) float  g_h   [(size_t)NN * HC];   // GEMM out (fp32)
__device__ __align__(16) __half g_ahi [(size_t)NN * HC];   // A hi (fp16)
__device__ __align__(16) __half g_alo [(size_t)NN * HC];   // A lo (fp16)
__device__ __align__(16) __half g_wt  [(size_t)HC * HC];   // W^T fp16  [N][K]
__device__ __align__(16) float g_als[(size_t)NN * HEADS];
__device__ __align__(16) float g_ald[(size_t)NN * HEADS];
__device__ __align__(16) float g_exv[(size_t)ETOT * HEADS];       // per-edge exp(logit)
__device__ int g_deg     [NN];
__device__ int g_rowstart[NN + 1];
__device__ int g_cursor  [NN];
__device__ int g_csr_src [ETOT];
__device__ int g_csr_dst [ETOT];

__device__ __forceinline__ void split2h(float v, __half& hi, __half& lo) {
    hi = __float2half_rn(v);
    lo = __float2half_rn(v - __half2float(hi));
}

__device__ __forceinline__ uint32_t smem_u32(const void* p) {
    uint32_t a;
    asm("{ .reg .u64 t; cvta.to.shared.u64 t, %1; cvt.u32.u64 %0, t; }"
        : "=r"(a) : "l"(p));
    return a;
}

// ================================ CSR build ==================================
__global__ void k_zero_deg(int* deg, int n) {
    int i = blockIdx.x * blockDim.x + threadIdx.x;
    if (i < n) deg[i] = 0;
}
__global__ void k_count(const int* __restrict__ ei, int E, int n, int* __restrict__ deg) {
    int e = blockIdx.x * blockDim.x + threadIdx.x;
    if (e >= E + n) return;
    int dst = (e < E) ? ei[E + e] : (e - E);
    atomicAdd(&deg[dst], 1);
}
__global__ void k_scan(const int* __restrict__ deg, int* __restrict__ rowstart,
                       int* __restrict__ cursor, int n) {
    __shared__ int sm[1024];
    int t = threadIdx.x;
    int CH = (n + 1023) >> 10;
    int lo = t * CH, hi = lo + CH; if (hi > n) hi = n;
    int loc = 0;
    for (int i = lo; i < hi; i++) loc += deg[i];
    sm[t] = loc;
    __syncthreads();
    for (int off = 1; off < 1024; off <<= 1) {
        int v = (t >= off) ? sm[t - off] : 0;
        __syncthreads();
        sm[t] += v;
        __syncthreads();
    }
    int run = sm[t] - loc;
    for (int i = lo; i < hi; i++) {
        rowstart[i] = run; cursor[i] = run; run += deg[i];
    }
    if (t == 1023) rowstart[n] = sm[1023];
}
__global__ void k_scatter(const int* __restrict__ ei, int E, int n,
                          int* __restrict__ cursor, int* __restrict__ csr_src,
                          int* __restrict__ csr_dst) {
    int e = blockIdx.x * blockDim.x + threadIdx.x;
    if (e >= E + n) return;
    int src, dst;
    if (e < E) { src = ei[e]; dst = ei[E + e]; }
    else       { src = e - E; dst = e - E; }
    int pos = atomicAdd(&cursor[dst], 1);
    csr_src[pos] = src;
    csr_dst[pos] = dst;
}

// ======================= fp32 -> fp16 conversions ============================
__global__ void k_split_x(const float* __restrict__ x, __half* __restrict__ hi,
                          __half* __restrict__ lo, int total) {
    int i = blockIdx.x * blockDim.x + threadIdx.x;
    if (i >= total) return;
    split2h(x[i], hi[i], lo[i]);
}
// W [K,N] fp32 -> Wt [N,K] fp16 (single rounding)
__global__ void k_cvt_wt(const float* __restrict__ W, __half* __restrict__ wt,
                         int K, int N) {
    int i = blockIdx.x * blockDim.x + threadIdx.x;
    if (i >= K * N) return;
    int k = i / N, n = i % N;
    wt[(size_t)n * K + k] = __float2half_rn(W[i]);
}

// =================== HMMA GEMM: C[M,N] = A[M,K] @ Wt[N,K]^T ==================
// A = Ah + Al (fp16 pair, exact to ~2^-22), B = fp16(W).  D = Ah*B + Al*B.
// BM=128, BN=128, BK=32; 8 warps (2x4), 64x32 warp tiles.
// cp.async 3-stage pipeline (wait_group 1), 92 KB dynamic smem, 2 CTAs/SM.

__device__ __forceinline__ void mma16816(float* d, const uint32_t* a, const uint32_t* b) {
    asm volatile(
        "mma.sync.aligned.m16n8k16.row.col.f32.f16.f16.f32 "
        "{%0,%1,%2,%3}, {%4,%5,%6,%7}, {%8,%9}, {%0,%1,%2,%3};"
        : "+f"(d[0]), "+f"(d[1]), "+f"(d[2]), "+f"(d[3])
        : "r"(a[0]), "r"(a[1]), "r"(a[2]), "r"(a[3]), "r"(b[0]), "r"(b[1]));
}
__device__ __forceinline__ void ldsm_x4(uint32_t* r, uint32_t addr) {
    asm volatile("ldmatrix.sync.aligned.m8n8.x4.shared.b16 {%0,%1,%2,%3}, [%4];"
                 : "=r"(r[0]), "=r"(r[1]), "=r"(r[2]), "=r"(r[3]) : "r"(addr));
}
__device__ __forceinline__ void ldsm_x2(uint32_t* r, uint32_t addr) {
    asm volatile("ldmatrix.sync.aligned.m8n8.x2.shared.b16 {%0,%1}, [%2];"
                 : "=r"(r[0]), "=r"(r[1]) : "r"(addr));
}
__device__ __forceinline__ void cp16(uint32_t dst, const void* src, int src_sz) {
    asm volatile("cp.async.cg.shared.global [%0], [%1], 16, %2;"
                 :: "r"(dst), "l"(src), "r"(src_sz));
}
#define CP_COMMIT() asm volatile("cp.async.commit_group;" ::: "memory")
#define CP_WAIT0()  asm volatile("cp.async.wait_group 0;" ::: "memory")
#define CP_WAIT1()  asm volatile("cp.async.wait_group 1;" ::: "memory")

#define LDPAD 40                       // 80-byte row stride, ldmatrix conflict-free
#define ROWB  (LDPAD * 2)              // 80
#define ARR_BYTES (128 * ROWB)         // 10240
#define OFF_AH 0
#define OFF_AL (1 * ARR_BYTES)
#define OFF_B  (2 * ARR_BYTES)
#define STAGE_BYTES (3 * ARR_BYTES)    // 30720
#define NSTAGE 3
#define GEMM_SMEM (NSTAGE * STAGE_BYTES)  // 92160

__global__ __launch_bounds__(256) void k_mma_gemm(
    const __half* __restrict__ Ahi, const __half* __restrict__ Alo,
    const __half* __restrict__ B,
    float* __restrict__ C, int M, int K, int N)
{
    extern __shared__ __align__(16) char smem[];
    const uint32_t sb = smem_u32(smem);

    const int tid = threadIdx.x;
    const int wid = tid >> 5, lane = tid & 31;
    const int wm0 = (wid & 1) * 64;
    const int wn0 = (wid >> 1) * 32;
    const int row0 = blockIdx.y * 128, col0 = blockIdx.x * 128;

    float acc[4][4][4];
    #pragma unroll
    for (int i = 0; i < 4; i++)
        #pragma unroll
        for (int j = 0; j < 4; j++)
            #pragma unroll
            for (int q = 0; q < 4; q++) acc[i][j][q] = 0.f;

    const int ldr = tid >> 2;              // 0..63
    const int ldq = (tid & 3) * 8;         // half offset (16B quantum)
    const uint32_t sdst = (uint32_t)(ldr * ROWB + ldq * 2);

    const int la = lane & 15;
    const uint32_t aoffs = (uint32_t)(((wm0 + la) * LDPAD + (lane >> 4) * 8) * 2);
    const uint32_t boffs = (uint32_t)(((wn0 + (la & 7)) * LDPAD + ((la >> 3) & 1) * 8) * 2);

    const int nch = K >> 5;

    auto issue = [&](int ch) {
        const int k0 = ch << 5;
        const uint32_t stb = sb + (uint32_t)(ch % NSTAGE) * STAGE_BYTES;
        #pragma unroll
        for (int i = 0; i < 2; i++) {
            const int r = ldr + i * 64;
            const uint32_t dd = sdst + (uint32_t)(i * 64 * ROWB);
            const int gr = row0 + r;
            const int ok = (gr < M) ? 16 : 0;
            const size_t ga = (size_t)(ok ? gr : 0) * K + k0 + ldq;
            cp16(stb + OFF_AH + dd, &Ahi[ga], ok);
            cp16(stb + OFF_AL + dd, &Alo[ga], ok);
            const size_t gb = (size_t)(col0 + r) * K + k0 + ldq;
            cp16(stb + OFF_B + dd, &B[gb], 16);
        }
        CP_COMMIT();
    };

    issue(0);
    if (nch > 1) issue(1);
    for (int ch = 0; ch < nch; ch++) {
        if (ch + 1 < nch) CP_WAIT1(); else CP_WAIT0();
        __syncthreads();                 // all warps done with stage (ch-1)%3
        if (ch + 2 < nch) issue(ch + 2); // refill that stage
        const uint32_t stb = sb + (uint32_t)(ch % NSTAGE) * STAGE_BYTES;
        const uint32_t aH = stb + OFF_AH + aoffs;
        const uint32_t aL = stb + OFF_AL + aoffs;
        const uint32_t bB = stb + OFF_B + boffs;
        #pragma unroll
        for (int stp = 0; stp < 2; stp++) {
            const uint32_t ko = stp * 32;
            uint32_t Ah[4][4], Al[4][4], Bf[4][2];
            #pragma unroll
            for (int i = 0; i < 4; i++) {
                ldsm_x4(Ah[i], aH + ko + (uint32_t)(i * 16 * ROWB));
                ldsm_x4(Al[i], aL + ko + (uint32_t)(i * 16 * ROWB));
            }
            #pragma unroll
            for (int j = 0; j < 4; j++)
                ldsm_x2(Bf[j], bB + ko + (uint32_t)(j * 8 * ROWB));
            #pragma unroll
            for (int i = 0; i < 4; i++)
                #pragma unroll
                for (int j = 0; j < 4; j++) {
                    mma16816(acc[i][j], Ah[i], Bf[j]);
                    mma16816(acc[i][j], Al[i], Bf[j]);
                }
        }
    }

    const int er = lane >> 2, ec = (lane & 3) * 2;
    #pragma unroll
    for (int i = 0; i < 4; i++) {
        #pragma unroll
        for (int j = 0; j < 4; j++) {
            int gr = row0 + wm0 + i * 16 + er;
            int gc = col0 + wn0 + j * 8 + ec;
            if (gr < M)
                *(float2*)&C[(size_t)gr * N + gc] = make_float2(acc[i][j][0], acc[i][j][1]);
            if (gr + 8 < M)
                *(float2*)&C[(size_t)(gr + 8) * N + gc] = make_float2(acc[i][j][2], acc[i][j][3]);
        }
    }
}

// ===================== per-node attention half-logits ========================
template<int H, int C>
__global__ __launch_bounds__(256) void k_attn_logits(
    const float* __restrict__ hfeat, const float* __restrict__ a_src,
    const float* __restrict__ a_dst, float* __restrict__ als,
    float* __restrict__ ald, int n)
{
    constexpr int HCc = H * C;
    constexpr int F = HCc / 32;
    constexpr int G = C / F;
    int warp = (blockIdx.x * blockDim.x + threadIdx.x) >> 5;
    int lane = threadIdx.x & 31;
    if (warp >= n) return;
    const float4* hp = (const float4*)&hfeat[(size_t)warp * HCc + lane * F];
    const float4* sp = (const float4*)&a_src[lane * F];
    const float4* dp = (const float4*)&a_dst[lane * F];
    float s1 = 0.f, s2 = 0.f;
    #pragma unroll
    for (int q = 0; q < F / 4; q++) {
        float4 v = hp[q], w1 = sp[q], w2 = dp[q];
        s1 += v.x * w1.x + v.y * w1.y + v.z * w1.z + v.w * w1.w;
        s2 += v.x * w2.x + v.y * w2.y + v.z * w2.z + v.w * w2.w;
    }
    #pragma unroll
    for (int o = 1; o < G; o <<= 1) {
        s1 += __shfl_xor_sync(0xffffffffu, s1, o);
        s2 += __shfl_xor_sync(0xffffffffu, s2, o);
    }
    if ((lane % G) == 0) {
        int hd = lane / G;
        als[(size_t)warp * H + hd] = s1;
        ald[(size_t)warp * H + hd] = s2;
    }
}

// ============== edge-parallel exp(leaky(logit)) — one exp per (edge,head) ====
template<int H>
__global__ __launch_bounds__(256) void k_edge_exp(
    const float* __restrict__ als, const float* __restrict__ ald,
    const int* __restrict__ csr_src, const int* __restrict__ csr_dst,
    float* __restrict__ exv, int etot)
{
    int j = blockIdx.x * blockDim.x + threadIdx.x;
    if (j >= etot) return;
    int s = csr_src[j], d = csr_dst[j];
    if (H == 8) {
        const float4* as = (const float4*)&als[(size_t)s * 8];
        const float4* ad = (const float4*)&ald[(size_t)d * 8];
        float4* ev = (float4*)&exv[(size_t)j * 8];
        #pragma unroll
        for (int q = 0; q < 2; q++) {
            float4 a = as[q], b = ad[q], r;
            float v;
            v = a.x + b.x; v = (v > 0.f) ? v : NEG_SLOPE * v; r.x = __expf(v);
            v = a.y + b.y; v = (v > 0.f) ? v : NEG_SLOPE * v; r.y = __expf(v);
            v = a.z + b.z; v = (v > 0.f) ? v : NEG_SLOPE * v; r.z = __expf(v);
            v = a.w + b.w; v = (v > 0.f) ? v : NEG_SLOPE * v; r.w = __expf(v);
            ev[q] = r;
        }
    } else {
        float v = als[s] + ald[d];
        v = (v > 0.f) ? v : NEG_SLOPE * v;
        exv[j] = __expf(v);
    }
}

// ======= single-pass weighted aggregate: acc = Σ ev·h, normalize at end ======
template<int H, int C, bool ELU, bool SPLIT>
__global__ __launch_bounds__(256) void k_gat_aggregate(
    const float* __restrict__ hfeat, const float* __restrict__ exv,
    const int* __restrict__ rowstart, const int* __restrict__ csr_src,
    const float* __restrict__ bias, float* __restrict__ out,
    __half* __restrict__ ohi, __half* __restrict__ olo, int n)
{
    constexpr int HCc = H * C;
    constexpr int F = HCc / 32;
    constexpr int V = F / 4;
    int warp = (blockIdx.x * blockDim.x + threadIdx.x) >> 5;
    int lane = threadIdx.x & 31;
    if (warp >= n) return;
    const int d = warp;
    const int start = rowstart[d], end = rowstart[d + 1];
    const int myhead = (lane * F) / C;

    float den = 0.f;
    float4 acc[V];
    #pragma unroll
    for (int q = 0; q < V; q++) acc[q] = make_float4(0.f, 0.f, 0.f, 0.f);

    for (int j = start; j < end; j++) {
        int s = csr_src[j];
        float ev = exv[(size_t)j * H + myhead];
        den += ev;
        const float4* hp = (const float4*)&hfeat[(size_t)s * HCc + lane * F];
        #pragma unroll
        for (int q = 0; q < V; q++) {
            float4 t = hp[q];
            acc[q].x += ev * t.x; acc[q].y += ev * t.y;
            acc[q].z += ev * t.z; acc[q].w += ev * t.w;
        }
    }

    const float inv = 1.0f / den;   // den >= exp(self-loop logit) > 0
    const float4* bp = (const float4*)&bias[lane * F];
    #pragma unroll
    for (int q = 0; q < V; q++) {
        float4 b = bp[q];
        acc[q].x = acc[q].x * inv + b.x;
        acc[q].y = acc[q].y * inv + b.y;
        acc[q].z = acc[q].z * inv + b.z;
        acc[q].w = acc[q].w * inv + b.w;
        if (ELU) {
            acc[q].x = (acc[q].x > 0.f) ? acc[q].x : (__expf(acc[q].x) - 1.f);
            acc[q].y = (acc[q].y > 0.f) ? acc[q].y : (__expf(acc[q].y) - 1.f);
            acc[q].z = (acc[q].z > 0.f) ? acc[q].z : (__expf(acc[q].z) - 1.f);
            acc[q].w = (acc[q].w > 0.f) ? acc[q].w : (__expf(acc[q].w) - 1.f);
        }
    }

    if (SPLIT) {
        __half hv[F], lv[F];
        const float* av = (const float*)acc;
        #pragma unroll
        for (int f = 0; f < F; f++) split2h(av[f], hv[f], lv[f]);
        size_t base = (size_t)d * HCc + lane * F;
        #pragma unroll
        for (int q = 0; q < (F * 2) / 16; q++) {
            *(uint4*)&ohi[base + q * 8] = ((const uint4*)hv)[q];
            *(uint4*)&olo[base + q * 8] = ((const uint4*)lv)[q];
        }
    } else {
        float* op = &out[(size_t)d * HCc + lane * F];
        #pragma unroll
        for (int q = 0; q < V; q++) *(float4*)(op + q * 4) = acc[q];
    }
}

// ================================ launch =====================================
extern "C" void kernel_launch(void* const* d_in, const int* in_sizes, int n_in,
                              void* d_out, int out_size) {
    const float* x      = (const float*)d_in[0];
    const int*   ei     = (const int*)d_in[1];
    const float* W1     = (const float*)d_in[2];
    const float* a_src1 = (const float*)d_in[3];
    const float* a_dst1 = (const float*)d_in[4];
    const float* b1     = (const float*)d_in[5];
    const float* W2     = (const float*)d_in[6];
    const float* a_src2 = (const float*)d_in[7];
    const float* a_dst2 = (const float*)d_in[8];
    const float* b2     = (const float*)d_in[9];
    const float* W3     = (const float*)d_in[10];
    const float* a_src3 = (const float*)d_in[11];
    const float* a_dst3 = (const float*)d_in[12];
    const float* b3     = (const float*)d_in[13];
    float* out = (float*)d_out;

    const int n = NN;
    const int E = in_sizes[1] / 2;
    const int etot = E + n;

    float *hbuf, *als, *ald, *exv;
    __half *ahi, *alo, *wt;
    int *deg, *rowstart, *cursor, *csr_src, *csr_dst;
    cudaGetSymbolAddress((void**)&hbuf,     g_h);
    cudaGetSymbolAddress((void**)&ahi,      g_ahi);
    cudaGetSymbolAddress((void**)&alo,      g_alo);
    cudaGetSymbolAddress((void**)&wt,       g_wt);
    cudaGetSymbolAddress((void**)&als,      g_als);
    cudaGetSymbolAddress((void**)&ald,      g_ald);
    cudaGetSymbolAddress((void**)&exv,      g_exv);
    cudaGetSymbolAddress((void**)&deg,      g_deg);
    cudaGetSymbolAddress((void**)&rowstart, g_rowstart);
    cudaGetSymbolAddress((void**)&cursor,   g_cursor);
    cudaGetSymbolAddress((void**)&csr_src,  g_csr_src);
    cudaGetSymbolAddress((void**)&csr_dst,  g_csr_dst);

    cudaFuncSetAttribute(k_mma_gemm, cudaFuncAttributeMaxDynamicSharedMemorySize, GEMM_SMEM);

    const int warp_blocks = (n + 7) / 8;
    const int edge_blocks = (etot + 255) / 256;
    const int Mtiles = (n + 127) / 128;

    // layer-1 GEMM first (keeps it in ncu's sampling slot)
    k_zero_deg<<<(n + 255) / 256, 256>>>(deg, n);
    k_split_x<<<(n * IN_DIM + 255) / 256, 256>>>(x, ahi, alo, n * IN_DIM);
    k_cvt_wt<<<(IN_DIM * HC + 255) / 256, 256>>>(W1, wt, IN_DIM, HC);
    k_mma_gemm<<<dim3(HC / 128, Mtiles), 256, GEMM_SMEM>>>(ahi, alo, wt, hbuf, n, IN_DIM, HC);

    // CSR build
    k_count<<<edge_blocks, 256>>>(ei, E, n, deg);
    k_scan<<<1, 1024>>>(deg, rowstart, cursor, n);
    k_scatter<<<edge_blocks, 256>>>(ei, E, n, cursor, csr_src, csr_dst);

    // --- layer 1 attention + aggregate ---
    k_attn_logits<HEADS, HID><<<warp_blocks, 256>>>(hbuf, a_src1, a_dst1, als, ald, n);
    k_edge_exp<HEADS><<<edge_blocks, 256>>>(als, ald, csr_src, csr_dst, exv, etot);
    k_gat_aggregate<HEADS, HID, true, true><<<warp_blocks, 256>>>(
        hbuf, exv, rowstart, csr_src, b1, nullptr, ahi, alo, n);

    // --- layer 2 ---
    k_cvt_wt<<<(HC * HC + 255) / 256, 256>>>(W2, wt, HC, HC);
    k_mma_gemm<<<dim3(HC / 128, Mtiles), 256, GEMM_SMEM>>>(ahi, alo, wt, hbuf, n, HC, HC);
    k_attn_logits<HEADS, HID><<<warp_blocks, 256>>>(hbuf, a_src2, a_dst2, als, ald, n);
    k_edge_exp<HEADS><<<edge_blocks, 256>>>(als, ald, csr_src, csr_dst, exv, etot);
    k_gat_aggregate<HEADS, HID, true, true><<<warp_blocks, 256>>>(
        hbuf, exv, rowstart, csr_src, b2, nullptr, ahi, alo, n);

    // --- layer 3: 512 -> 128, heads=1, no concat ---
    k_cvt_wt<<<(HC * OUT_DIM + 255) / 256, 256>>>(W3, wt, HC, OUT_DIM);
    k_mma_gemm<<<dim3(OUT_DIM / 128, Mtiles), 256, GEMM_SMEM>>>(ahi, alo, wt, hbuf, n, HC, OUT_DIM);
    k_attn_logits<1, OUT_DIM><<<warp_blocks, 256>>>(hbuf, a_src3, a_dst3, als, ald, n);
    k_edge_exp<1><<<edge_blocks, 256>>>(als, ald, csr_src, csr_dst, exv, etot);
    k_gat_aggregate<1, OUT_DIM, false, false><<<warp_blocks, 256>>>(
        hbuf, exv, rowstart, csr_src, b3, out, nullptr, nullptr, n);
}